// round 15
// baseline (speedup 1.0000x reference)
#include <cuda_runtime.h>
#include <cuda_bf16.h>
#include <math.h>
#include <stdint.h>

// Problem constants
#define B_  8192
#define N_  32
#define D_  128
#define M_  384
#define H_  2
#define DK_ 192

typedef __nv_bfloat16 bf16;

// ---------------------------------------------------------------------------
// Static device scratch
// ---------------------------------------------------------------------------
__device__ __align__(16) float g_Tq[2 * 256 * 192];
__device__ __align__(16) float g_Tk[2 * 384 * 192];
__device__ __align__(16) float g_Tv[2 * 384 * 192];
__device__ __align__(16) float g_Qt[(size_t)B_ * 768];        // fp32 (attn input)
__device__ __align__(16) float g_Y[2 * (size_t)B_ * 384];     // fp32 split-K partials

// bf16 hi/lo operand buffers
__device__ __align__(16) bf16 g_qt_h[(size_t)B_ * 256], g_qt_l[(size_t)B_ * 256];   // [src|src_t]
__device__ __align__(16) bf16 g_cb_h[(size_t)B_ * 768], g_cb_l[(size_t)B_ * 768];
__device__ __align__(16) bf16 g_ys_h[(size_t)B_ * 512], g_ys_l[(size_t)B_ * 512];   // [LN(Y)|src]
__device__ __align__(16) bf16 g_hb_h[(size_t)B_ * 128], g_hb_l[(size_t)B_ * 128];
__device__ __align__(16) bf16 g_ah_h[768 * 256], g_ah_l[768 * 256];
__device__ __align__(16) bf16 g_bh_h[384 * 768], g_bh_l[384 * 768];
__device__ __align__(16) bf16 g_w1_h[128 * 512], g_w1_l[128 * 512];
__device__ __align__(16) bf16 g_w2_h[128 * 128], g_w2_l[128 * 128];

// ---------------------------------------------------------------------------
// PTX helpers (baseline PTX: valid at compute_103)
// ---------------------------------------------------------------------------
__device__ __forceinline__ uint32_t smem_u32(const void* p) {
    uint32_t a;
    asm("{ .reg .u64 t; cvta.to.shared.u64 t, %1; cvt.u32.u64 %0, t; }"
        : "=r"(a) : "l"(p));
    return a;
}

__device__ __forceinline__ void mma_bf16(float* d, const uint32_t* a, const uint32_t* b) {
    asm volatile(
        "mma.sync.aligned.m16n8k16.row.col.f32.bf16.bf16.f32 "
        "{%0,%1,%2,%3}, {%4,%5,%6,%7}, {%8,%9}, {%0,%1,%2,%3};"
        : "+f"(d[0]), "+f"(d[1]), "+f"(d[2]), "+f"(d[3])
        : "r"(a[0]), "r"(a[1]), "r"(a[2]), "r"(a[3]), "r"(b[0]), "r"(b[1]));
}

__device__ __forceinline__ void ldmx4(uint32_t* r, uint32_t addr) {
    asm volatile("ldmatrix.sync.aligned.m8n8.x4.shared.b16 {%0,%1,%2,%3}, [%4];"
        : "=r"(r[0]), "=r"(r[1]), "=r"(r[2]), "=r"(r[3]) : "r"(addr));
}

__device__ __forceinline__ void cpa16(uint32_t s, const void* g) {
    asm volatile("cp.async.cg.shared.global [%0], [%1], 16;" :: "r"(s), "l"(g));
}
#define CPA_COMMIT() asm volatile("cp.async.commit_group;")
#define CPA_WAIT2()  asm volatile("cp.async.wait_group 2;")
#define CPA_WAIT1()  asm volatile("cp.async.wait_group 1;")
#define CPA_WAIT0()  asm volatile("cp.async.wait_group 0;")

// fp32 -> bf16 hi/lo split, two elements packed per word
__device__ __forceinline__ void bsplit(float a, float b, uint32_t& hi, uint32_t& lo) {
    bf16 ha = __float2bfloat16_rn(a), hb = __float2bfloat16_rn(b);
    bf16 la = __float2bfloat16_rn(a - __bfloat162float(ha));
    bf16 lb = __float2bfloat16_rn(b - __bfloat162float(hb));
    hi = ((uint32_t)__bfloat16_as_ushort(hb) << 16) | (uint32_t)__bfloat16_as_ushort(ha);
    lo = ((uint32_t)__bfloat16_as_ushort(lb) << 16) | (uint32_t)__bfloat16_as_ushort(la);
}

// ---------------------------------------------------------------------------
// COMPUTE core (warp tile 32x32, BK=32, bf16x3)
// ---------------------------------------------------------------------------
#define STG 24576

__device__ __forceinline__ void compute_ks(
    uint32_t base, int ks, int mw, int nw, int lt, int lr, float acc[2][4][4])
{
    uint32_t Ah[2][4], Al[2][4], Bh[4][2], Bl[4][2];
#pragma unroll
    for (int mt = 0; mt < 2; mt++) {
        int m  = mw + mt * 16 + ((lt & 1) << 3) + lr;
        int cc = ks * 2 + (lt >> 1);
        uint32_t off = (uint32_t)(m * 64 + ((cc ^ ((m >> 1) & 3)) << 4));
        ldmx4(Ah[mt], base + off);
        ldmx4(Al[mt], base + 8192u + off);
    }
#pragma unroll
    for (int p = 0; p < 2; p++) {
        int n  = nw + ((2 * p + (lt >> 1)) << 3) + lr;
        int cc = ks * 2 + (lt & 1);
        uint32_t off = (uint32_t)(n * 64 + ((cc ^ ((n >> 1) & 3)) << 4));
        uint32_t t[4];
        ldmx4(t, base + 16384u + off);
        Bh[2 * p][0] = t[0]; Bh[2 * p][1] = t[1];
        Bh[2 * p + 1][0] = t[2]; Bh[2 * p + 1][1] = t[3];
        ldmx4(t, base + 20480u + off);
        Bl[2 * p][0] = t[0]; Bl[2 * p][1] = t[1];
        Bl[2 * p + 1][0] = t[2]; Bl[2 * p + 1][1] = t[3];
    }
#pragma unroll
    for (int mt = 0; mt < 2; mt++)
#pragma unroll
        for (int nt = 0; nt < 4; nt++) {
            mma_bf16(acc[mt][nt], Ah[mt], Bh[nt]);
            mma_bf16(acc[mt][nt], Ah[mt], Bl[nt]);
            mma_bf16(acc[mt][nt], Al[mt], Bh[nt]);
        }
}

// Epilogue fragment writer (fp32 OR bf16 hi/lo)
__device__ __forceinline__ void epilogue(
    int bm, int bn, int mw, int nw, int lane, float acc[2][4][4],
    const float* bias, float scale, int do_relu,
    float* outf, bf16* ohi, bf16* olo, int ldc)
{
    const int er = lane >> 2, ec = (lane & 3) << 1;
#pragma unroll
    for (int mt = 0; mt < 2; mt++)
#pragma unroll
        for (int nt = 0; nt < 4; nt++) {
            int row = bm + mw + mt * 16 + er;
            int col = bn + nw + nt * 8 + ec;
            float b0 = bias ? bias[col] : 0.f;
            float b1 = bias ? bias[col + 1] : 0.f;
            float v0 = acc[mt][nt][0] * scale + b0;
            float v1 = acc[mt][nt][1] * scale + b1;
            float v2 = acc[mt][nt][2] * scale + b0;
            float v3 = acc[mt][nt][3] * scale + b1;
            if (do_relu) {
                v0 = fmaxf(v0, 0.f); v1 = fmaxf(v1, 0.f);
                v2 = fmaxf(v2, 0.f); v3 = fmaxf(v3, 0.f);
            }
            if (outf) {
                *(float2*)(outf + (size_t)row * ldc + col)       = make_float2(v0, v1);
                *(float2*)(outf + (size_t)(row + 8) * ldc + col) = make_float2(v2, v3);
            } else {
                uint32_t h, l;
                bsplit(v0, v1, h, l);
                *(uint32_t*)(ohi + (size_t)row * ldc + col) = h;
                *(uint32_t*)(olo + (size_t)row * ldc + col) = l;
                bsplit(v2, v3, h, l);
                *(uint32_t*)(ohi + (size_t)(row + 8) * ldc + col) = h;
                *(uint32_t*)(olo + (size_t)(row + 8) * ldc + col) = l;
            }
        }
}

// ---------------------------------------------------------------------------
// GEMM: 4-stage cp.async, tile-stride loop, split-K slices.
// ---------------------------------------------------------------------------
__global__ __launch_bounds__(256, 2) void mma_gemm_bf(
    const bf16* __restrict__ Ahi, const bf16* __restrict__ Alo, int lda,
    const bf16* __restrict__ Whi, const bf16* __restrict__ Wlo, int ldw,
    const float* __restrict__ bias,
    float* __restrict__ outf, bf16* __restrict__ ohi, bf16* __restrict__ olo,
    int ldc, int K, float scale, int do_relu, int nTiles, int gx,
    int perSlice, int aOfs, int wOfs, size_t oOfs)
{
    extern __shared__ __align__(1024) char smbuf[];
    const uint32_t smA = smem_u32(smbuf);

    const int tid  = threadIdx.x;
    const int lane = tid & 31, wid = tid >> 5;
    const int mw = (wid >> 1) * 32;
    const int nw = (wid & 1) * 32;
    const int lt = lane >> 3, lr = lane & 7;
    const int nch = K >> 5;

    const int ar0 = tid >> 2, aq = tid & 3;
    const int ar1 = ar0 + 64;
    const uint32_t aoff0 = (uint32_t)(ar0 * 64 + ((aq ^ ((ar0 >> 1) & 3)) << 4));
    const uint32_t aoff1 = (uint32_t)(ar1 * 64 + ((aq ^ ((ar1 >> 1) & 3)) << 4));
    const uint32_t boff  = aoff0;

    for (int t = blockIdx.x; t < nTiles; t += gridDim.x) {
        const int ksl = t / perSlice;
        const int tt  = t - ksl * perSlice;
        const int bm = (tt / gx) * 128, bn = (tt % gx) * 64;

        const bf16* pAh = Ahi + (size_t)ksl * aOfs;
        const bf16* pAl = Alo + (size_t)ksl * aOfs;
        const bf16* pWh = Whi + (size_t)ksl * wOfs;
        const bf16* pWl = Wlo + (size_t)ksl * wOfs;
        float* pOf = outf ? (outf + (size_t)ksl * oOfs) : (float*)0;

        float acc[2][4][4];
#pragma unroll
        for (int i = 0; i < 2; i++)
#pragma unroll
            for (int j = 0; j < 4; j++)
#pragma unroll
                for (int q = 0; q < 4; q++) acc[i][j][q] = 0.f;

        auto COPY = [&](int c) {
            const uint32_t st = smA + (uint32_t)(c & 3) * STG;
            const int k0 = c << 5;
            cpa16(st + aoff0,         pAh + (size_t)(bm + ar0) * lda + k0 + aq * 8);
            cpa16(st + 8192u + aoff0, pAl + (size_t)(bm + ar0) * lda + k0 + aq * 8);
            cpa16(st + aoff1,         pAh + (size_t)(bm + ar1) * lda + k0 + aq * 8);
            cpa16(st + 8192u + aoff1, pAl + (size_t)(bm + ar1) * lda + k0 + aq * 8);
            cpa16(st + 16384u + boff, pWh + (size_t)(bn + ar0) * ldw + k0 + aq * 8);
            cpa16(st + 20480u + boff, pWl + (size_t)(bn + ar0) * ldw + k0 + aq * 8);
        };

        COPY(0); CPA_COMMIT();
        COPY(1); CPA_COMMIT();
        COPY(2); CPA_COMMIT();

        for (int c = 0; c < nch; c++) {
            CPA_WAIT2();
            __syncthreads();
            const uint32_t base = smA + (uint32_t)(c & 3) * STG;
            compute_ks(base, 0, mw, nw, lt, lr, acc);
            compute_ks(base, 1, mw, nw, lt, lr, acc);
            if (c + 3 < nch) COPY(c + 3);
            CPA_COMMIT();
        }
        CPA_WAIT0();

        epilogue(bm, bn, mw, nw, lane, acc, bias, scale, do_relu, pOf, ohi, olo, ldc);
        __syncthreads();
    }
}

// ---------------------------------------------------------------------------
// fp32-input GEMM body (2-stage, in-loop conversion) for the precompute GEMMs.
// ---------------------------------------------------------------------------
__device__ __forceinline__ void gemm_f32_body(
    const float* __restrict__ A0, int lda,
    const float* __restrict__ W, int ldw,
    bf16* __restrict__ ohi, bf16* __restrict__ olo,
    int ldc, int K, float scale, int bm, int bn, char* smraw)
{
    const int tid  = threadIdx.x;
    const int lane = tid & 31, wid = tid >> 5;
    const int mw = (wid >> 1) * 32;
    const int nw = (wid & 1) * 32;
    const int lt = lane >> 3, lr = lane & 7;

    float acc[2][4][4];
#pragma unroll
    for (int i = 0; i < 2; i++)
#pragma unroll
        for (int j = 0; j < 4; j++)
#pragma unroll
            for (int q = 0; q < 4; q++) acc[i][j][q] = 0.f;

    const uint32_t smA = smem_u32(smraw);
    const int nch = K >> 5;

    float4 ra[4], rb[2];

    auto LOAD = [&](int c) {
        const int k0 = c << 5;
#pragma unroll
        for (int i = 0; i < 4; i++) {
            int lin = tid + (i << 8);
            int r = lin >> 3, q = lin & 7;
            ra[i] = *(const float4*)(A0 + (size_t)(bm + r) * lda + k0 + (q << 2));
        }
#pragma unroll
        for (int i = 0; i < 2; i++) {
            int lin = tid + (i << 8);
            int r = lin >> 3, q = lin & 7;
            rb[i] = *(const float4*)(W + (size_t)(bn + r) * ldw + k0 + (q << 2));
        }
    };

    auto STORE = [&](int s) {
        char* st = smraw + s * STG;
#pragma unroll
        for (int i = 0; i < 4; i++) {
            int lin = tid + (i << 8);
            int r = lin >> 3, q = lin & 7;
            uint32_t h0, l0, h1, l1;
            bsplit(ra[i].x, ra[i].y, h0, l0);
            bsplit(ra[i].z, ra[i].w, h1, l1);
            uint32_t off = (uint32_t)(r * 64 + (((q >> 1) ^ ((r >> 1) & 3)) << 4) + ((q & 1) << 3));
            *(uint2*)(st + off)        = make_uint2(h0, h1);
            *(uint2*)(st + 8192 + off) = make_uint2(l0, l1);
        }
#pragma unroll
        for (int i = 0; i < 2; i++) {
            int lin = tid + (i << 8);
            int r = lin >> 3, q = lin & 7;
            uint32_t h0, l0, h1, l1;
            bsplit(rb[i].x, rb[i].y, h0, l0);
            bsplit(rb[i].z, rb[i].w, h1, l1);
            uint32_t off = (uint32_t)(r * 64 + (((q >> 1) ^ ((r >> 1) & 3)) << 4) + ((q & 1) << 3));
            *(uint2*)(st + 16384 + off) = make_uint2(h0, h1);
            *(uint2*)(st + 20480 + off) = make_uint2(l0, l1);
        }
    };

    LOAD(0); STORE(0); __syncthreads();
    for (int c = 0; c < nch; c++) {
        const int more = (c + 1 < nch);
        if (more) LOAD(c + 1);
        const uint32_t base = smA + (uint32_t)(c & 1) * STG;
        compute_ks(base, 0, mw, nw, lt, lr, acc);
        if (more) STORE((c + 1) & 1);
        compute_ks(base, 1, mw, nw, lt, lr, acc);
        __syncthreads();
    }

    epilogue(bm, bn, mw, nw, lane, acc, nullptr, scale, 0, nullptr, ohi, olo, ldc);
}

// ---------------------------------------------------------------------------
// One launch: CTAs 0..59 compute Ahat + Bhat; CTAs 60.. do elementwise converts.
// ---------------------------------------------------------------------------
__global__ __launch_bounds__(256, 2) void precompute_kernel(
    const float* __restrict__ Tk, const float* __restrict__ Tq,
    const float* __restrict__ Tv, const float* __restrict__ fc_w,
    bf16* __restrict__ ahh, bf16* __restrict__ ahl,
    bf16* __restrict__ bhh, bf16* __restrict__ bhl, float invs,
    const float* __restrict__ src, const float* __restrict__ srct,
    const float* __restrict__ w1, const float* __restrict__ w2,
    bf16* __restrict__ qh, bf16* __restrict__ ql,
    bf16* __restrict__ ysh, bf16* __restrict__ ysl,
    bf16* __restrict__ w1h, bf16* __restrict__ w1l,
    bf16* __restrict__ w2h, bf16* __restrict__ w2l)
{
    __shared__ __align__(1024) char smbuf[2 * STG];
    int id = blockIdx.x;
    if (id < 24) {
        int head = id / 12, t = id % 12;
        gemm_f32_body(Tk + (size_t)head * 384 * 192, 192,
                      Tq + (size_t)head * 256 * 192, 192,
                      ahh + (size_t)head * 384 * 256, ahl + (size_t)head * 384 * 256,
                      256, 192, invs, (t / 4) * 128, (t % 4) * 64, smbuf);
    } else if (id < 60) {
        id -= 24;
        int head = id / 18, t = id % 18;
        gemm_f32_body(fc_w + head * 192, 384,
                      Tv + (size_t)head * 384 * 192, 192,
                      bhh + head * 384, bhl + head * 384,
                      768, 192, 1.f, (t / 6) * 128, (t % 6) * 64, smbuf);
    } else {
        const int nconv = gridDim.x - 60;
        const int stride = nconv * 256;
        for (int idx = (blockIdx.x - 60) * 256 + threadIdx.x;
             idx < B_ * 64; idx += stride) {
            int b = idx >> 6, d2 = idx & 63;
            float2 s  = ((const float2*)src)[(size_t)b * 64 + d2];
            float2 st = ((const float2*)srct)[(size_t)b * 64 + d2];
            uint32_t h, l;
            bsplit(s.x, s.y, h, l);
            ((uint32_t*)qh)[(size_t)b * 128 + d2] = h;
            ((uint32_t*)ql)[(size_t)b * 128 + d2] = l;
            ((uint32_t*)ysh)[(size_t)b * 256 + 192 + d2] = h;
            ((uint32_t*)ysl)[(size_t)b * 256 + 192 + d2] = l;
            bsplit(st.x, st.y, h, l);
            ((uint32_t*)qh)[(size_t)b * 128 + 64 + d2] = h;
            ((uint32_t*)ql)[(size_t)b * 128 + 64 + d2] = l;
            if (idx < 128 * 512 / 2) {
                float2 v = ((const float2*)w1)[idx];
                uint32_t hh, ll;
                bsplit(v.x, v.y, hh, ll);
                ((uint32_t*)w1h)[idx] = hh;
                ((uint32_t*)w1l)[idx] = ll;
            }
            if (idx < 128 * 128 / 2) {
                float2 v = ((const float2*)w2)[idx];
                uint32_t hh, ll;
                bsplit(v.x, v.y, hh, ll);
                ((uint32_t*)w2h)[idx] = hh;
                ((uint32_t*)w2l)[idx] = ll;
            }
        }
    }
}

// ---------------------------------------------------------------------------
// Merged weight transposes
// ---------------------------------------------------------------------------
__global__ void prep_transpose(const float* __restrict__ w_q,
                               const float* __restrict__ w_k,
                               const float* __restrict__ w_v,
                               float* __restrict__ Tq, float* __restrict__ Tk,
                               float* __restrict__ Tv)
{
    __shared__ float tile[32][33];
    const int z = blockIdx.z;
    const int h = z & 1;
    const float* src; float* dst; int cols, split, shift;
    if (z < 2)      { src = w_q; dst = Tq; cols = 256; split = 128; shift = 128; }
    else if (z < 4) { src = w_k; dst = Tk; cols = 384; split = 384; shift = 0; }
    else            { src = w_v; dst = Tv; cols = 384; split = 384; shift = 0; }

    const int c0 = blockIdx.x * 32;
    if (c0 >= cols) return;
    const int d0 = blockIdx.y * 32;
    const int tx = threadIdx.x, ty = threadIdx.y;

#pragma unroll
    for (int r = 0; r < 4; r++) {
        int d = d0 + ty + r * 8;
        int c = c0 + tx;
        int cm = (c < split) ? c : c + shift;
        tile[ty + r * 8][tx] = src[(size_t)(h * 192 + d) * 384 + cm];
    }
    __syncthreads();
#pragma unroll
    for (int r = 0; r < 4; r++) {
        int c = c0 + ty + r * 8;
        int d = d0 + tx;
        dst[(size_t)(h * cols + c) * 192 + d] = tile[tx][ty + r * 8];
    }
}

// ---------------------------------------------------------------------------
// Persistent double-buffered attention (R15):
//  - redundant warp-local softmax (probs in registers, no at[] smem)
//  - C phase: 192 threads, float2, probs via shfl
//  - 3 syncthreads per batch (was 4)
// KSTRIDE=392 (≡ 8 mod 32): conflict-free score phase.
// ---------------------------------------------------------------------------
#define KSTRIDE 392
#define KTILE_W (32 * KSTRIDE)

__global__ __launch_bounds__(256, 2) void attn_kernel(
    const float* __restrict__ Qt,
    const float* __restrict__ seq,
    const float* __restrict__ seq_e,
    const float* __restrict__ seq_t,
    const int*   __restrict__ mask,
    bf16* __restrict__ Cbh, bf16* __restrict__ Cbl,
    float* __restrict__ attn_out)
{
    extern __shared__ __align__(1024) char dynsm[];
    float* kb0 = (float*)dynsm;                 // 2 x KTILE_W
    float* qs0 = kb0 + 2 * KTILE_W;             // 2 x 768
    float* sc  = qs0 + 2 * 768;                 // 64

    const int tid = threadIdx.x;
    const int lane = tid & 31, wid = tid >> 5;
    const uint32_t kbb = smem_u32(kb0);
    const uint32_t qsb = smem_u32(qs0);

    const int nb = (B_ - blockIdx.x + gridDim.x - 1) / gridDim.x;

    auto ISSUE = [&](int b, int s) {
        const uint32_t kd = kbb + (uint32_t)s * (KTILE_W * 4);
#pragma unroll
        for (int l = 0; l < 12; l++) {
            int i4  = tid + (l << 8);
            int n   = i4 / 96;
            int jq  = i4 - n * 96;
            int seg = jq >> 5;
            int dq  = jq & 31;
            const float* p = (seg == 0) ? seq : ((seg == 1) ? seq_e : seq_t);
            cpa16(kd + (uint32_t)(n * KSTRIDE + jq * 4) * 4u,
                  p + ((size_t)(b * 32 + n)) * 128 + dq * 4);
        }
        if (tid < 192)
            cpa16(qsb + (uint32_t)s * 3072u + (uint32_t)tid * 16u,
                  Qt + (size_t)b * 768 + tid * 4);
    };

    ISSUE(blockIdx.x, 0); CPA_COMMIT();

    for (int i = 0; i < nb; i++) {
        const int b = blockIdx.x + i * gridDim.x;
        const int more = (i + 1 < nb);
        if (more) { ISSUE(b + gridDim.x, (i + 1) & 1); CPA_COMMIT(); }
        if (more) { CPA_WAIT1(); } else { CPA_WAIT0(); }
        __syncthreads();

        const int s = i & 1;
        const float* kbuf = kb0 + s * KTILE_W;
        const float* qs   = qs0 + s * 768;

        // Scores: 8 lanes per n, both heads (each k element read once)
        {
            int n  = tid >> 3;
            int ql = tid & 7;
            const float* kr = kbuf + n * KSTRIDE;
            const float* q0 = qs;
            const float* q1 = qs + 384;
            float s0 = 0.f, s1 = 0.f;
#pragma unroll 8
            for (int j = ql; j < 384; j += 8) {
                float kv = kr[j];
                s0 += kv * q0[j];
                s1 += kv * q1[j];
            }
#pragma unroll
            for (int o = 4; o > 0; o >>= 1) {
                s0 += __shfl_xor_sync(0xffffffffu, s0, o);
                s1 += __shfl_xor_sync(0xffffffffu, s1, o);
            }
            if (ql == 0) {
                bool msk = (mask[b * 32 + n] != 0);
                sc[n]      = msk ? -1e10f : s0;
                sc[32 + n] = msk ? -1e10f : s1;
            }
        }
        __syncthreads();

        // Redundant warp-local softmax: every warp computes both heads;
        // probs stay in registers (lane = n).
        float p0, p1;
        {
            float v0 = sc[lane], v1 = sc[32 + lane];
            float m0 = v0, m1 = v1;
#pragma unroll
            for (int o = 16; o > 0; o >>= 1) {
                m0 = fmaxf(m0, __shfl_xor_sync(0xffffffffu, m0, o));
                m1 = fmaxf(m1, __shfl_xor_sync(0xffffffffu, m1, o));
            }
            float e0 = expf(v0 - m0), e1 = expf(v1 - m1);
            float t0 = e0, t1 = e1;
#pragma unroll
            for (int o = 16; o > 0; o >>= 1) {
                t0 += __shfl_xor_sync(0xffffffffu, t0, o);
                t1 += __shfl_xor_sync(0xffffffffu, t1, o);
            }
            p0 = e0 / t0;
            p1 = e1 / t1;
            if (wid == 0)
                attn_out[(size_t)b * 32 + lane] = p0;
            else if (wid == 1)
                attn_out[((size_t)B_ + b) * 32 + lane] = p1;
        }
        // no barrier needed: probs are warp-local registers

        // C phase: 192 threads, 2 cols each (float2); probs via shfl
        if (tid < 192) {
            const int j = tid * 2;
            float c00 = 0.f, c01 = 0.f, c10 = 0.f, c11 = 0.f;
#pragma unroll
            for (int n = 0; n < 32; n++) {
                float2 kv = *(const float2*)(kbuf + n * KSTRIDE + j);
                float w0 = __shfl_sync(0xffffffffu, p0, n);
                float w1 = __shfl_sync(0xffffffffu, p1, n);
                c00 += w0 * kv.x; c01 += w0 * kv.y;
                c10 += w1 * kv.x; c11 += w1 * kv.y;
            }
            uint32_t* CH = (uint32_t*)Cbh + (size_t)b * 384;
            uint32_t* CL = (uint32_t*)Cbl + (size_t)b * 384;
            uint32_t h, l;
            bsplit(c00, c01, h, l);
            CH[tid] = h; CL[tid] = l;
            bsplit(c10, c11, h, l);
            CH[192 + tid] = h; CL[192 + tid] = l;
        }
        __syncthreads();   // buffer s fully consumed before iter i+1 overwrites it
    }
}

// ---------------------------------------------------------------------------
// LayerNorm: sums 2 split-K partials + fc_b, writes YS hi/lo
// ---------------------------------------------------------------------------
__global__ __launch_bounds__(256) void ln_kernel(
    const float* __restrict__ Y0,
    const float* __restrict__ fc_b,
    const float* __restrict__ ln_g,
    const float* __restrict__ ln_b,
    bf16* __restrict__ ysh, bf16* __restrict__ ysl)
{
    const int row  = blockIdx.x * 8 + (threadIdx.x >> 5);
    const int lane = threadIdx.x & 31;
    const float* y0 = Y0 + (size_t)row * 384;
    const float* y1 = y0 + (size_t)B_ * 384;

    float2 v[6];
    float s = 0.f;
#pragma unroll
    for (int i = 0; i < 6; i++) {
        int c = 2 * lane + 64 * i;
        float2 a0 = *(const float2*)(y0 + c);
        float2 a1 = *(const float2*)(y1 + c);
        v[i].x = a0.x + a1.x + fc_b[c];
        v[i].y = a0.y + a1.y + fc_b[c + 1];
        s += v[i].x + v[i].y;
    }
#pragma unroll
    for (int o = 16; o > 0; o >>= 1) s += __shfl_xor_sync(0xffffffffu, s, o);
    float mu = s * (1.f / 384.f);

    float q = 0.f;
#pragma unroll
    for (int i = 0; i < 6; i++) {
        float d0 = v[i].x - mu, d1 = v[i].y - mu;
        q += d0 * d0 + d1 * d1;
    }
#pragma unroll
    for (int o = 16; o > 0; o >>= 1) q += __shfl_xor_sync(0xffffffffu, q, o);
    float inv = rsqrtf(q * (1.f / 384.f) + 1e-5f);

#pragma unroll
    for (int i = 0; i < 6; i++) {
        int c = 2 * lane + 64 * i;
        float yy0 = (v[i].x - mu) * inv * ln_g[c] + ln_b[c];
        float yy1 = (v[i].y - mu) * inv * ln_g[c + 1] + ln_b[c + 1];
        uint32_t h, l;
        bsplit(yy0, yy1, h, l);
        ((uint32_t*)ysh)[(size_t)row * 256 + lane + 32 * i] = h;
        ((uint32_t*)ysl)[(size_t)row * 256 + lane + 32 * i] = l;
    }
}

// ---------------------------------------------------------------------------
// Launch
// ---------------------------------------------------------------------------
extern "C" void kernel_launch(void* const* d_in, const int* in_sizes, int n_in,
                              void* d_out, int out_size)
{
    const float* src   = (const float*)d_in[0];
    const float* src_t = (const float*)d_in[1];
    const float* seq   = (const float*)d_in[2];
    const float* seq_t = (const float*)d_in[3];
    const float* seq_e = (const float*)d_in[4];
    const int*   mask  = (const int*)d_in[6];
    const float* w_q   = (const float*)d_in[7];
    const float* w_k   = (const float*)d_in[8];
    const float* w_v   = (const float*)d_in[9];
    const float* fc_w  = (const float*)d_in[10];
    const float* fc_b  = (const float*)d_in[11];
    const float* ln_g  = (const float*)d_in[12];
    const float* ln_b  = (const float*)d_in[13];
    const float* mg_w1 = (const float*)d_in[14];
    const float* mg_b1 = (const float*)d_in[15];
    const float* mg_w2 = (const float*)d_in[16];
    const float* mg_b2 = (const float*)d_in[17];
    float* out = (float*)d_out;
    float* merged_out = out;
    float* attn_out   = out + (size_t)B_ * D_;

    float *Tq, *Tk, *Tv, *Qt, *Y;
    bf16 *qth, *qtl, *cbh, *cbl, *ysh, *ysl, *hbh, *hbl;
    bf16 *ahh, *ahl, *bhh, *bhl, *w1h, *w1l, *w2h, *w2l;
    cudaGetSymbolAddress((void**)&Tq, g_Tq);
    cudaGetSymbolAddress((void**)&Tk, g_Tk);
    cudaGetSymbolAddress((void**)&Tv, g_Tv);
    cudaGetSymbolAddress((void**)&Qt, g_Qt);
    cudaGetSymbolAddress((void**)&Y,  g_Y);
    cudaGetSymbolAddress((void**)&qth, g_qt_h); cudaGetSymbolAddress((void**)&qtl, g_qt_l);
    cudaGetSymbolAddress((void**)&cbh, g_cb_h); cudaGetSymbolAddress((void**)&cbl, g_cb_l);
    cudaGetSymbolAddress((void**)&ysh, g_ys_h); cudaGetSymbolAddress((void**)&ysl, g_ys_l);
    cudaGetSymbolAddress((void**)&hbh, g_hb_h); cudaGetSymbolAddress((void**)&hbl, g_hb_l);
    cudaGetSymbolAddress((void**)&ahh, g_ah_h); cudaGetSymbolAddress((void**)&ahl, g_ah_l);
    cudaGetSymbolAddress((void**)&bhh, g_bh_h); cudaGetSymbolAddress((void**)&bhl, g_bh_l);
    cudaGetSymbolAddress((void**)&w1h, g_w1_h); cudaGetSymbolAddress((void**)&w1l, g_w1_l);
    cudaGetSymbolAddress((void**)&w2h, g_w2_h); cudaGetSymbolAddress((void**)&w2l, g_w2_l);

    const int ATTN_SMEM = (2 * KTILE_W + 2 * 768 + 64) * (int)sizeof(float); // ~107 KB
    cudaFuncSetAttribute(attn_kernel, cudaFuncAttributeMaxDynamicSharedMemorySize, ATTN_SMEM);
    cudaFuncSetAttribute(mma_gemm_bf, cudaFuncAttributeMaxDynamicSharedMemorySize, 4 * STG);

    // 1. weight transposes
    prep_transpose<<<dim3(12, 6, 6), dim3(32, 8)>>>(w_q, w_k, w_v, Tq, Tk, Tv);

    const float invs = (float)(1.0 / sqrt((double)DK_));

    // 2. Ahat + Bhat GEMM tiles + elementwise converts
    precompute_kernel<<<296, 256>>>(Tk, Tq, Tv, fc_w, ahh, ahl, bhh, bhl, invs,
                                    src, src_t, mg_w1, mg_w2,
                                    qth, qtl, ysh, ysl, w1h, w1l, w2h, w2l);

    // 3. Qt = [src|src_t] @ Ahat^T  (768 tiles, K=256)
    mma_gemm_bf<<<296, 256, 4 * STG>>>(
        qth, qtl, 256, ahh, ahl, 256, nullptr,
        Qt, nullptr, nullptr, 768, 256, 1.f, 0, 768, 12,
        768, 0, 0, 0);

    // 4. persistent attention -> Cb hi/lo, attn_w
    attn_kernel<<<296, 256, ATTN_SMEM>>>(Qt, seq, seq_e, seq_t, mask, cbh, cbl, attn_out);

    // 5. Y partials: split-K=2 over heads (768 tiles of K=384)
    mma_gemm_bf<<<296, 256, 4 * STG>>>(
        cbh, cbl, 768, bhh, bhl, 768, nullptr,
        Y, nullptr, nullptr, 384, 384, 1.f, 0, 768, 6,
        384, 384, 384, (size_t)B_ * 384);

    // 6. LayerNorm (sums partials + fc_b) -> YS hi/lo
    ln_kernel<<<B_ / 8, 256>>>(Y, fc_b, ln_g, ln_b, ysh, ysl);

    // 7. Hb = relu(YS @ w1^T + b1)  (128 tiles, K=512) -> hi/lo
    mma_gemm_bf<<<128, 256, 4 * STG>>>(
        ysh, ysl, 512, w1h, w1l, 512, mg_b1,
        nullptr, hbh, hbl, 128, 512, 1.f, 1, 128, 2,
        128, 0, 0, 0);

    // 8. merged = Hb @ w2^T + b2  (128 tiles, K=128)
    mma_gemm_bf<<<128, 256, 4 * STG>>>(
        hbh, hbl, 128, w2h, w2l, 128, mg_b2,
        merged_out, nullptr, nullptr, 128, 128, 1.f, 0, 128, 2,
        128, 0, 0, 0);

    (void)in_sizes; (void)n_in; (void)out_size; (void)seq_t;
}

// round 16
// speedup vs baseline: 1.0774x; 1.0774x over previous
#include <cuda_runtime.h>
#include <cuda_bf16.h>
#include <math.h>
#include <stdint.h>

// Problem constants
#define B_  8192
#define N_  32
#define D_  128
#define M_  384
#define H_  2
#define DK_ 192

typedef __nv_bfloat16 bf16;

// ---------------------------------------------------------------------------
// Static device scratch
// ---------------------------------------------------------------------------
__device__ __align__(16) float g_Tq[2 * 256 * 192];
__device__ __align__(16) float g_Tk[2 * 384 * 192];
__device__ __align__(16) float g_Tv[2 * 384 * 192];
__device__ __align__(16) float g_Qt[(size_t)B_ * 768];        // fp32 (attn input)
__device__ __align__(16) float g_Y[2 * (size_t)B_ * 384];     // fp32 split-K partials

// bf16 hi/lo operand buffers
__device__ __align__(16) bf16 g_qt_h[(size_t)B_ * 256], g_qt_l[(size_t)B_ * 256];   // [src|src_t]
__device__ __align__(16) bf16 g_cb_h[(size_t)B_ * 768], g_cb_l[(size_t)B_ * 768];
__device__ __align__(16) bf16 g_ys_h[(size_t)B_ * 512], g_ys_l[(size_t)B_ * 512];   // [LN(Y)|src]
__device__ __align__(16) bf16 g_hb_h[(size_t)B_ * 128], g_hb_l[(size_t)B_ * 128];
__device__ __align__(16) bf16 g_ah_h[768 * 256], g_ah_l[768 * 256];
__device__ __align__(16) bf16 g_bh_h[384 * 768], g_bh_l[384 * 768];
__device__ __align__(16) bf16 g_w1_h[128 * 512], g_w1_l[128 * 512];
__device__ __align__(16) bf16 g_w2_h[128 * 128], g_w2_l[128 * 128];

// ---------------------------------------------------------------------------
// PTX helpers (baseline PTX: valid at compute_103)
// ---------------------------------------------------------------------------
__device__ __forceinline__ uint32_t smem_u32(const void* p) {
    uint32_t a;
    asm("{ .reg .u64 t; cvta.to.shared.u64 t, %1; cvt.u32.u64 %0, t; }"
        : "=r"(a) : "l"(p));
    return a;
}

__device__ __forceinline__ void mma_bf16(float* d, const uint32_t* a, const uint32_t* b) {
    asm volatile(
        "mma.sync.aligned.m16n8k16.row.col.f32.bf16.bf16.f32 "
        "{%0,%1,%2,%3}, {%4,%5,%6,%7}, {%8,%9}, {%0,%1,%2,%3};"
        : "+f"(d[0]), "+f"(d[1]), "+f"(d[2]), "+f"(d[3])
        : "r"(a[0]), "r"(a[1]), "r"(a[2]), "r"(a[3]), "r"(b[0]), "r"(b[1]));
}

__device__ __forceinline__ void ldmx4(uint32_t* r, uint32_t addr) {
    asm volatile("ldmatrix.sync.aligned.m8n8.x4.shared.b16 {%0,%1,%2,%3}, [%4];"
        : "=r"(r[0]), "=r"(r[1]), "=r"(r[2]), "=r"(r[3]) : "r"(addr));
}

__device__ __forceinline__ void cpa16(uint32_t s, const void* g) {
    asm volatile("cp.async.cg.shared.global [%0], [%1], 16;" :: "r"(s), "l"(g));
}
#define CPA_COMMIT() asm volatile("cp.async.commit_group;")
#define CPA_WAIT2()  asm volatile("cp.async.wait_group 2;")
#define CPA_WAIT1()  asm volatile("cp.async.wait_group 1;")
#define CPA_WAIT0()  asm volatile("cp.async.wait_group 0;")

// fp32 -> bf16 hi/lo split, two elements packed per word
__device__ __forceinline__ void bsplit(float a, float b, uint32_t& hi, uint32_t& lo) {
    bf16 ha = __float2bfloat16_rn(a), hb = __float2bfloat16_rn(b);
    bf16 la = __float2bfloat16_rn(a - __bfloat162float(ha));
    bf16 lb = __float2bfloat16_rn(b - __bfloat162float(hb));
    hi = ((uint32_t)__bfloat16_as_ushort(hb) << 16) | (uint32_t)__bfloat16_as_ushort(ha);
    lo = ((uint32_t)__bfloat16_as_ushort(lb) << 16) | (uint32_t)__bfloat16_as_ushort(la);
}

// ---------------------------------------------------------------------------
// COMPUTE core (warp tile 32x32, BK=32, bf16x3)
// ---------------------------------------------------------------------------
#define STG 24576

__device__ __forceinline__ void compute_ks(
    uint32_t base, int ks, int mw, int nw, int lt, int lr, float acc[2][4][4])
{
    uint32_t Ah[2][4], Al[2][4], Bh[4][2], Bl[4][2];
#pragma unroll
    for (int mt = 0; mt < 2; mt++) {
        int m  = mw + mt * 16 + ((lt & 1) << 3) + lr;
        int cc = ks * 2 + (lt >> 1);
        uint32_t off = (uint32_t)(m * 64 + ((cc ^ ((m >> 1) & 3)) << 4));
        ldmx4(Ah[mt], base + off);
        ldmx4(Al[mt], base + 8192u + off);
    }
#pragma unroll
    for (int p = 0; p < 2; p++) {
        int n  = nw + ((2 * p + (lt >> 1)) << 3) + lr;
        int cc = ks * 2 + (lt & 1);
        uint32_t off = (uint32_t)(n * 64 + ((cc ^ ((n >> 1) & 3)) << 4));
        uint32_t t[4];
        ldmx4(t, base + 16384u + off);
        Bh[2 * p][0] = t[0]; Bh[2 * p][1] = t[1];
        Bh[2 * p + 1][0] = t[2]; Bh[2 * p + 1][1] = t[3];
        ldmx4(t, base + 20480u + off);
        Bl[2 * p][0] = t[0]; Bl[2 * p][1] = t[1];
        Bl[2 * p + 1][0] = t[2]; Bl[2 * p + 1][1] = t[3];
    }
#pragma unroll
    for (int mt = 0; mt < 2; mt++)
#pragma unroll
        for (int nt = 0; nt < 4; nt++) {
            mma_bf16(acc[mt][nt], Ah[mt], Bh[nt]);
            mma_bf16(acc[mt][nt], Ah[mt], Bl[nt]);
            mma_bf16(acc[mt][nt], Al[mt], Bh[nt]);
        }
}

// Epilogue fragment writer (fp32 OR bf16 hi/lo)
__device__ __forceinline__ void epilogue(
    int bm, int bn, int mw, int nw, int lane, float acc[2][4][4],
    const float* bias, float scale, int do_relu,
    float* outf, bf16* ohi, bf16* olo, int ldc)
{
    const int er = lane >> 2, ec = (lane & 3) << 1;
#pragma unroll
    for (int mt = 0; mt < 2; mt++)
#pragma unroll
        for (int nt = 0; nt < 4; nt++) {
            int row = bm + mw + mt * 16 + er;
            int col = bn + nw + nt * 8 + ec;
            float b0 = bias ? bias[col] : 0.f;
            float b1 = bias ? bias[col + 1] : 0.f;
            float v0 = acc[mt][nt][0] * scale + b0;
            float v1 = acc[mt][nt][1] * scale + b1;
            float v2 = acc[mt][nt][2] * scale + b0;
            float v3 = acc[mt][nt][3] * scale + b1;
            if (do_relu) {
                v0 = fmaxf(v0, 0.f); v1 = fmaxf(v1, 0.f);
                v2 = fmaxf(v2, 0.f); v3 = fmaxf(v3, 0.f);
            }
            if (outf) {
                *(float2*)(outf + (size_t)row * ldc + col)       = make_float2(v0, v1);
                *(float2*)(outf + (size_t)(row + 8) * ldc + col) = make_float2(v2, v3);
            } else {
                uint32_t h, l;
                bsplit(v0, v1, h, l);
                *(uint32_t*)(ohi + (size_t)row * ldc + col) = h;
                *(uint32_t*)(olo + (size_t)row * ldc + col) = l;
                bsplit(v2, v3, h, l);
                *(uint32_t*)(ohi + (size_t)(row + 8) * ldc + col) = h;
                *(uint32_t*)(olo + (size_t)(row + 8) * ldc + col) = l;
            }
        }
}

// ---------------------------------------------------------------------------
// GEMM: 4-stage cp.async, tile-stride loop, split-K slices.
// ---------------------------------------------------------------------------
__global__ __launch_bounds__(256, 2) void mma_gemm_bf(
    const bf16* __restrict__ Ahi, const bf16* __restrict__ Alo, int lda,
    const bf16* __restrict__ Whi, const bf16* __restrict__ Wlo, int ldw,
    const float* __restrict__ bias,
    float* __restrict__ outf, bf16* __restrict__ ohi, bf16* __restrict__ olo,
    int ldc, int K, float scale, int do_relu, int nTiles, int gx,
    int perSlice, int aOfs, int wOfs, size_t oOfs)
{
    extern __shared__ __align__(1024) char smbuf[];
    const uint32_t smA = smem_u32(smbuf);

    const int tid  = threadIdx.x;
    const int lane = tid & 31, wid = tid >> 5;
    const int mw = (wid >> 1) * 32;
    const int nw = (wid & 1) * 32;
    const int lt = lane >> 3, lr = lane & 7;
    const int nch = K >> 5;

    const int ar0 = tid >> 2, aq = tid & 3;
    const int ar1 = ar0 + 64;
    const uint32_t aoff0 = (uint32_t)(ar0 * 64 + ((aq ^ ((ar0 >> 1) & 3)) << 4));
    const uint32_t aoff1 = (uint32_t)(ar1 * 64 + ((aq ^ ((ar1 >> 1) & 3)) << 4));
    const uint32_t boff  = aoff0;

    for (int t = blockIdx.x; t < nTiles; t += gridDim.x) {
        const int ksl = t / perSlice;
        const int tt  = t - ksl * perSlice;
        const int bm = (tt / gx) * 128, bn = (tt % gx) * 64;

        const bf16* pAh = Ahi + (size_t)ksl * aOfs;
        const bf16* pAl = Alo + (size_t)ksl * aOfs;
        const bf16* pWh = Whi + (size_t)ksl * wOfs;
        const bf16* pWl = Wlo + (size_t)ksl * wOfs;
        float* pOf = outf ? (outf + (size_t)ksl * oOfs) : (float*)0;

        float acc[2][4][4];
#pragma unroll
        for (int i = 0; i < 2; i++)
#pragma unroll
            for (int j = 0; j < 4; j++)
#pragma unroll
                for (int q = 0; q < 4; q++) acc[i][j][q] = 0.f;

        auto COPY = [&](int c) {
            const uint32_t st = smA + (uint32_t)(c & 3) * STG;
            const int k0 = c << 5;
            cpa16(st + aoff0,         pAh + (size_t)(bm + ar0) * lda + k0 + aq * 8);
            cpa16(st + 8192u + aoff0, pAl + (size_t)(bm + ar0) * lda + k0 + aq * 8);
            cpa16(st + aoff1,         pAh + (size_t)(bm + ar1) * lda + k0 + aq * 8);
            cpa16(st + 8192u + aoff1, pAl + (size_t)(bm + ar1) * lda + k0 + aq * 8);
            cpa16(st + 16384u + boff, pWh + (size_t)(bn + ar0) * ldw + k0 + aq * 8);
            cpa16(st + 20480u + boff, pWl + (size_t)(bn + ar0) * ldw + k0 + aq * 8);
        };

        COPY(0); CPA_COMMIT();
        COPY(1); CPA_COMMIT();
        COPY(2); CPA_COMMIT();

        for (int c = 0; c < nch; c++) {
            CPA_WAIT2();
            __syncthreads();
            const uint32_t base = smA + (uint32_t)(c & 3) * STG;
            compute_ks(base, 0, mw, nw, lt, lr, acc);
            compute_ks(base, 1, mw, nw, lt, lr, acc);
            if (c + 3 < nch) COPY(c + 3);
            CPA_COMMIT();
        }
        CPA_WAIT0();

        epilogue(bm, bn, mw, nw, lane, acc, bias, scale, do_relu, pOf, ohi, olo, ldc);
        __syncthreads();
    }
}

// ---------------------------------------------------------------------------
// fp32-input GEMM body (2-stage, in-loop conversion) for the precompute GEMMs.
// ---------------------------------------------------------------------------
__device__ __forceinline__ void gemm_f32_body(
    const float* __restrict__ A0, int lda,
    const float* __restrict__ W, int ldw,
    bf16* __restrict__ ohi, bf16* __restrict__ olo,
    int ldc, int K, float scale, int bm, int bn, char* smraw)
{
    const int tid  = threadIdx.x;
    const int lane = tid & 31, wid = tid >> 5;
    const int mw = (wid >> 1) * 32;
    const int nw = (wid & 1) * 32;
    const int lt = lane >> 3, lr = lane & 7;

    float acc[2][4][4];
#pragma unroll
    for (int i = 0; i < 2; i++)
#pragma unroll
        for (int j = 0; j < 4; j++)
#pragma unroll
            for (int q = 0; q < 4; q++) acc[i][j][q] = 0.f;

    const uint32_t smA = smem_u32(smraw);
    const int nch = K >> 5;

    float4 ra[4], rb[2];

    auto LOAD = [&](int c) {
        const int k0 = c << 5;
#pragma unroll
        for (int i = 0; i < 4; i++) {
            int lin = tid + (i << 8);
            int r = lin >> 3, q = lin & 7;
            ra[i] = *(const float4*)(A0 + (size_t)(bm + r) * lda + k0 + (q << 2));
        }
#pragma unroll
        for (int i = 0; i < 2; i++) {
            int lin = tid + (i << 8);
            int r = lin >> 3, q = lin & 7;
            rb[i] = *(const float4*)(W + (size_t)(bn + r) * ldw + k0 + (q << 2));
        }
    };

    auto STORE = [&](int s) {
        char* st = smraw + s * STG;
#pragma unroll
        for (int i = 0; i < 4; i++) {
            int lin = tid + (i << 8);
            int r = lin >> 3, q = lin & 7;
            uint32_t h0, l0, h1, l1;
            bsplit(ra[i].x, ra[i].y, h0, l0);
            bsplit(ra[i].z, ra[i].w, h1, l1);
            uint32_t off = (uint32_t)(r * 64 + (((q >> 1) ^ ((r >> 1) & 3)) << 4) + ((q & 1) << 3));
            *(uint2*)(st + off)        = make_uint2(h0, h1);
            *(uint2*)(st + 8192 + off) = make_uint2(l0, l1);
        }
#pragma unroll
        for (int i = 0; i < 2; i++) {
            int lin = tid + (i << 8);
            int r = lin >> 3, q = lin & 7;
            uint32_t h0, l0, h1, l1;
            bsplit(rb[i].x, rb[i].y, h0, l0);
            bsplit(rb[i].z, rb[i].w, h1, l1);
            uint32_t off = (uint32_t)(r * 64 + (((q >> 1) ^ ((r >> 1) & 3)) << 4) + ((q & 1) << 3));
            *(uint2*)(st + 16384 + off) = make_uint2(h0, h1);
            *(uint2*)(st + 20480 + off) = make_uint2(l0, l1);
        }
    };

    LOAD(0); STORE(0); __syncthreads();
    for (int c = 0; c < nch; c++) {
        const int more = (c + 1 < nch);
        if (more) LOAD(c + 1);
        const uint32_t base = smA + (uint32_t)(c & 1) * STG;
        compute_ks(base, 0, mw, nw, lt, lr, acc);
        if (more) STORE((c + 1) & 1);
        compute_ks(base, 1, mw, nw, lt, lr, acc);
        __syncthreads();
    }

    epilogue(bm, bn, mw, nw, lane, acc, nullptr, scale, 0, nullptr, ohi, olo, ldc);
}

// ---------------------------------------------------------------------------
// One launch: CTAs 0..59 compute Ahat + Bhat; CTAs 60.. do elementwise converts.
// ---------------------------------------------------------------------------
__global__ __launch_bounds__(256, 2) void precompute_kernel(
    const float* __restrict__ Tk, const float* __restrict__ Tq,
    const float* __restrict__ Tv, const float* __restrict__ fc_w,
    bf16* __restrict__ ahh, bf16* __restrict__ ahl,
    bf16* __restrict__ bhh, bf16* __restrict__ bhl, float invs,
    const float* __restrict__ src, const float* __restrict__ srct,
    const float* __restrict__ w1, const float* __restrict__ w2,
    bf16* __restrict__ qh, bf16* __restrict__ ql,
    bf16* __restrict__ ysh, bf16* __restrict__ ysl,
    bf16* __restrict__ w1h, bf16* __restrict__ w1l,
    bf16* __restrict__ w2h, bf16* __restrict__ w2l)
{
    __shared__ __align__(1024) char smbuf[2 * STG];
    int id = blockIdx.x;
    if (id < 24) {
        int head = id / 12, t = id % 12;
        gemm_f32_body(Tk + (size_t)head * 384 * 192, 192,
                      Tq + (size_t)head * 256 * 192, 192,
                      ahh + (size_t)head * 384 * 256, ahl + (size_t)head * 384 * 256,
                      256, 192, invs, (t / 4) * 128, (t % 4) * 64, smbuf);
    } else if (id < 60) {
        id -= 24;
        int head = id / 18, t = id % 18;
        gemm_f32_body(fc_w + head * 192, 384,
                      Tv + (size_t)head * 384 * 192, 192,
                      bhh + head * 384, bhl + head * 384,
                      768, 192, 1.f, (t / 6) * 128, (t % 6) * 64, smbuf);
    } else {
        const int nconv = gridDim.x - 60;
        const int stride = nconv * 256;
        for (int idx = (blockIdx.x - 60) * 256 + threadIdx.x;
             idx < B_ * 64; idx += stride) {
            int b = idx >> 6, d2 = idx & 63;
            float2 s  = ((const float2*)src)[(size_t)b * 64 + d2];
            float2 st = ((const float2*)srct)[(size_t)b * 64 + d2];
            uint32_t h, l;
            bsplit(s.x, s.y, h, l);
            ((uint32_t*)qh)[(size_t)b * 128 + d2] = h;
            ((uint32_t*)ql)[(size_t)b * 128 + d2] = l;
            ((uint32_t*)ysh)[(size_t)b * 256 + 192 + d2] = h;
            ((uint32_t*)ysl)[(size_t)b * 256 + 192 + d2] = l;
            bsplit(st.x, st.y, h, l);
            ((uint32_t*)qh)[(size_t)b * 128 + 64 + d2] = h;
            ((uint32_t*)ql)[(size_t)b * 128 + 64 + d2] = l;
            if (idx < 128 * 512 / 2) {
                float2 v = ((const float2*)w1)[idx];
                uint32_t hh, ll;
                bsplit(v.x, v.y, hh, ll);
                ((uint32_t*)w1h)[idx] = hh;
                ((uint32_t*)w1l)[idx] = ll;
            }
            if (idx < 128 * 128 / 2) {
                float2 v = ((const float2*)w2)[idx];
                uint32_t hh, ll;
                bsplit(v.x, v.y, hh, ll);
                ((uint32_t*)w2h)[idx] = hh;
                ((uint32_t*)w2l)[idx] = ll;
            }
        }
    }
}

// ---------------------------------------------------------------------------
// Merged weight transposes
// ---------------------------------------------------------------------------
__global__ void prep_transpose(const float* __restrict__ w_q,
                               const float* __restrict__ w_k,
                               const float* __restrict__ w_v,
                               float* __restrict__ Tq, float* __restrict__ Tk,
                               float* __restrict__ Tv)
{
    __shared__ float tile[32][33];
    const int z = blockIdx.z;
    const int h = z & 1;
    const float* src; float* dst; int cols, split, shift;
    if (z < 2)      { src = w_q; dst = Tq; cols = 256; split = 128; shift = 128; }
    else if (z < 4) { src = w_k; dst = Tk; cols = 384; split = 384; shift = 0; }
    else            { src = w_v; dst = Tv; cols = 384; split = 384; shift = 0; }

    const int c0 = blockIdx.x * 32;
    if (c0 >= cols) return;
    const int d0 = blockIdx.y * 32;
    const int tx = threadIdx.x, ty = threadIdx.y;

#pragma unroll
    for (int r = 0; r < 4; r++) {
        int d = d0 + ty + r * 8;
        int c = c0 + tx;
        int cm = (c < split) ? c : c + shift;
        tile[ty + r * 8][tx] = src[(size_t)(h * 192 + d) * 384 + cm];
    }
    __syncthreads();
#pragma unroll
    for (int r = 0; r < 4; r++) {
        int c = c0 + ty + r * 8;
        int d = d0 + tx;
        dst[(size_t)(h * cols + c) * 192 + d] = tile[tx][ty + r * 8];
    }
}

// ---------------------------------------------------------------------------
// Persistent double-buffered attention (R14 structure):
//  - score phase: each warp owns 4 n-rows, q cached in registers per strip
//    (q smem reads drop 4x; k read once)
//  - softmax: warps 0/1 (as R14)
//  - C phase: 96 threads, float4 (as R14)
// KSTRIDE=392 (≡ 8 mod 32).
// ---------------------------------------------------------------------------
#define KSTRIDE 392
#define KTILE_W (32 * KSTRIDE)

__global__ __launch_bounds__(256, 2) void attn_kernel(
    const float* __restrict__ Qt,
    const float* __restrict__ seq,
    const float* __restrict__ seq_e,
    const float* __restrict__ seq_t,
    const int*   __restrict__ mask,
    bf16* __restrict__ Cbh, bf16* __restrict__ Cbl,
    float* __restrict__ attn_out)
{
    extern __shared__ __align__(1024) char dynsm[];
    float* kb0 = (float*)dynsm;                 // 2 x KTILE_W
    float* qs0 = kb0 + 2 * KTILE_W;             // 2 x 768
    float* sc  = qs0 + 2 * 768;                 // 64
    float* at  = sc + 64;                       // 64

    const int tid = threadIdx.x;
    const int lane = tid & 31, wid = tid >> 5;
    const uint32_t kbb = smem_u32(kb0);
    const uint32_t qsb = smem_u32(qs0);

    const int nb = (B_ - blockIdx.x + gridDim.x - 1) / gridDim.x;

    auto ISSUE = [&](int b, int s) {
        const uint32_t kd = kbb + (uint32_t)s * (KTILE_W * 4);
#pragma unroll
        for (int l = 0; l < 12; l++) {
            int i4  = tid + (l << 8);
            int n   = i4 / 96;
            int jq  = i4 - n * 96;
            int seg = jq >> 5;
            int dq  = jq & 31;
            const float* p = (seg == 0) ? seq : ((seg == 1) ? seq_e : seq_t);
            cpa16(kd + (uint32_t)(n * KSTRIDE + jq * 4) * 4u,
                  p + ((size_t)(b * 32 + n)) * 128 + dq * 4);
        }
        if (tid < 192)
            cpa16(qsb + (uint32_t)s * 3072u + (uint32_t)tid * 16u,
                  Qt + (size_t)b * 768 + tid * 4);
    };

    ISSUE(blockIdx.x, 0); CPA_COMMIT();

    for (int i = 0; i < nb; i++) {
        const int b = blockIdx.x + i * gridDim.x;
        const int more = (i + 1 < nb);
        if (more) { ISSUE(b + gridDim.x, (i + 1) & 1); CPA_COMMIT(); }
        if (more) { CPA_WAIT1(); } else { CPA_WAIT0(); }
        __syncthreads();

        const int s = i & 1;
        const float* kbuf = kb0 + s * KTILE_W;
        const float* qs   = qs0 + s * 768;

        // Scores: warp w owns n = 4w..4w+3; q loaded once per warp per strip.
        {
            const int n0 = wid * 4;
            float a00 = 0.f, a01 = 0.f, a10 = 0.f, a11 = 0.f,
                  a20 = 0.f, a21 = 0.f, a30 = 0.f, a31 = 0.f;
            const float* k0r = kbuf + (n0 + 0) * KSTRIDE;
            const float* k1r = kbuf + (n0 + 1) * KSTRIDE;
            const float* k2r = kbuf + (n0 + 2) * KSTRIDE;
            const float* k3r = kbuf + (n0 + 3) * KSTRIDE;
#pragma unroll
            for (int j0 = 0; j0 < 384; j0 += 32) {
                int j = j0 + lane;
                float q0 = qs[j];
                float q1 = qs[384 + j];
                float k0v = k0r[j], k1v = k1r[j], k2v = k2r[j], k3v = k3r[j];
                a00 += k0v * q0; a01 += k0v * q1;
                a10 += k1v * q0; a11 += k1v * q1;
                a20 += k2v * q0; a21 += k2v * q1;
                a30 += k3v * q0; a31 += k3v * q1;
            }
#pragma unroll
            for (int o = 16; o > 0; o >>= 1) {
                a00 += __shfl_xor_sync(0xffffffffu, a00, o);
                a01 += __shfl_xor_sync(0xffffffffu, a01, o);
                a10 += __shfl_xor_sync(0xffffffffu, a10, o);
                a11 += __shfl_xor_sync(0xffffffffu, a11, o);
                a20 += __shfl_xor_sync(0xffffffffu, a20, o);
                a21 += __shfl_xor_sync(0xffffffffu, a21, o);
                a30 += __shfl_xor_sync(0xffffffffu, a30, o);
                a31 += __shfl_xor_sync(0xffffffffu, a31, o);
            }
            if (lane < 4) {
                int n = n0 + lane;
                bool msk = (mask[b * 32 + n] != 0);
                float s0 = (lane == 0) ? a00 : (lane == 1) ? a10 : (lane == 2) ? a20 : a30;
                float s1 = (lane == 0) ? a01 : (lane == 1) ? a11 : (lane == 2) ? a21 : a31;
                sc[n]      = msk ? -1e10f : s0;
                sc[32 + n] = msk ? -1e10f : s1;
            }
        }
        __syncthreads();

        if (wid < 2) {
            float sv = sc[wid * 32 + lane];
            float m = sv;
#pragma unroll
            for (int o = 16; o > 0; o >>= 1)
                m = fmaxf(m, __shfl_xor_sync(0xffffffffu, m, o));
            float e = expf(sv - m);
            float sum = e;
#pragma unroll
            for (int o = 16; o > 0; o >>= 1)
                sum += __shfl_xor_sync(0xffffffffu, sum, o);
            float p = e / sum;
            at[wid * 32 + lane] = p;
            attn_out[((size_t)wid * B_ + b) * 32 + lane] = p;
        }
        __syncthreads();

        // C phase: thread t<96 owns cols j=4t; both heads per float4 k-read
        if (tid < 96) {
            const int j = tid * 4;
            float c00 = 0.f, c01 = 0.f, c02 = 0.f, c03 = 0.f;
            float c10 = 0.f, c11 = 0.f, c12 = 0.f, c13 = 0.f;
#pragma unroll
            for (int n = 0; n < 32; n++) {
                float4 kv = *(const float4*)(kbuf + n * KSTRIDE + j);
                float w0 = at[n], w1 = at[32 + n];
                c00 += w0 * kv.x; c01 += w0 * kv.y; c02 += w0 * kv.z; c03 += w0 * kv.w;
                c10 += w1 * kv.x; c11 += w1 * kv.y; c12 += w1 * kv.z; c13 += w1 * kv.w;
            }
            uint32_t* CH = (uint32_t*)Cbh + (size_t)b * 384;
            uint32_t* CL = (uint32_t*)Cbl + (size_t)b * 384;
            uint32_t h0, l0, h1, l1;
            bsplit(c00, c01, h0, l0); bsplit(c02, c03, h1, l1);
            *(uint2*)(CH + 2 * tid) = make_uint2(h0, h1);
            *(uint2*)(CL + 2 * tid) = make_uint2(l0, l1);
            bsplit(c10, c11, h0, l0); bsplit(c12, c13, h1, l1);
            *(uint2*)(CH + 192 + 2 * tid) = make_uint2(h0, h1);
            *(uint2*)(CL + 192 + 2 * tid) = make_uint2(l0, l1);
        }
        __syncthreads();   // buffer s fully consumed before iter i+1 overwrites it
    }
}

// ---------------------------------------------------------------------------
// LayerNorm: sums 2 split-K partials + fc_b, writes YS hi/lo
// ---------------------------------------------------------------------------
__global__ __launch_bounds__(256) void ln_kernel(
    const float* __restrict__ Y0,
    const float* __restrict__ fc_b,
    const float* __restrict__ ln_g,
    const float* __restrict__ ln_b,
    bf16* __restrict__ ysh, bf16* __restrict__ ysl)
{
    const int row  = blockIdx.x * 8 + (threadIdx.x >> 5);
    const int lane = threadIdx.x & 31;
    const float* y0 = Y0 + (size_t)row * 384;
    const float* y1 = y0 + (size_t)B_ * 384;

    float2 v[6];
    float s = 0.f;
#pragma unroll
    for (int i = 0; i < 6; i++) {
        int c = 2 * lane + 64 * i;
        float2 a0 = *(const float2*)(y0 + c);
        float2 a1 = *(const float2*)(y1 + c);
        v[i].x = a0.x + a1.x + fc_b[c];
        v[i].y = a0.y + a1.y + fc_b[c + 1];
        s += v[i].x + v[i].y;
    }
#pragma unroll
    for (int o = 16; o > 0; o >>= 1) s += __shfl_xor_sync(0xffffffffu, s, o);
    float mu = s * (1.f / 384.f);

    float q = 0.f;
#pragma unroll
    for (int i = 0; i < 6; i++) {
        float d0 = v[i].x - mu, d1 = v[i].y - mu;
        q += d0 * d0 + d1 * d1;
    }
#pragma unroll
    for (int o = 16; o > 0; o >>= 1) q += __shfl_xor_sync(0xffffffffu, q, o);
    float inv = rsqrtf(q * (1.f / 384.f) + 1e-5f);

#pragma unroll
    for (int i = 0; i < 6; i++) {
        int c = 2 * lane + 64 * i;
        float yy0 = (v[i].x - mu) * inv * ln_g[c] + ln_b[c];
        float yy1 = (v[i].y - mu) * inv * ln_g[c + 1] + ln_b[c + 1];
        uint32_t h, l;
        bsplit(yy0, yy1, h, l);
        ((uint32_t*)ysh)[(size_t)row * 256 + lane + 32 * i] = h;
        ((uint32_t*)ysl)[(size_t)row * 256 + lane + 32 * i] = l;
    }
}

// ---------------------------------------------------------------------------
// Launch
// ---------------------------------------------------------------------------
extern "C" void kernel_launch(void* const* d_in, const int* in_sizes, int n_in,
                              void* d_out, int out_size)
{
    const float* src   = (const float*)d_in[0];
    const float* src_t = (const float*)d_in[1];
    const float* seq   = (const float*)d_in[2];
    const float* seq_t = (const float*)d_in[3];
    const float* seq_e = (const float*)d_in[4];
    const int*   mask  = (const int*)d_in[6];
    const float* w_q   = (const float*)d_in[7];
    const float* w_k   = (const float*)d_in[8];
    const float* w_v   = (const float*)d_in[9];
    const float* fc_w  = (const float*)d_in[10];
    const float* fc_b  = (const float*)d_in[11];
    const float* ln_g  = (const float*)d_in[12];
    const float* ln_b  = (const float*)d_in[13];
    const float* mg_w1 = (const float*)d_in[14];
    const float* mg_b1 = (const float*)d_in[15];
    const float* mg_w2 = (const float*)d_in[16];
    const float* mg_b2 = (const float*)d_in[17];
    float* out = (float*)d_out;
    float* merged_out = out;
    float* attn_out   = out + (size_t)B_ * D_;

    float *Tq, *Tk, *Tv, *Qt, *Y;
    bf16 *qth, *qtl, *cbh, *cbl, *ysh, *ysl, *hbh, *hbl;
    bf16 *ahh, *ahl, *bhh, *bhl, *w1h, *w1l, *w2h, *w2l;
    cudaGetSymbolAddress((void**)&Tq, g_Tq);
    cudaGetSymbolAddress((void**)&Tk, g_Tk);
    cudaGetSymbolAddress((void**)&Tv, g_Tv);
    cudaGetSymbolAddress((void**)&Qt, g_Qt);
    cudaGetSymbolAddress((void**)&Y,  g_Y);
    cudaGetSymbolAddress((void**)&qth, g_qt_h); cudaGetSymbolAddress((void**)&qtl, g_qt_l);
    cudaGetSymbolAddress((void**)&cbh, g_cb_h); cudaGetSymbolAddress((void**)&cbl, g_cb_l);
    cudaGetSymbolAddress((void**)&ysh, g_ys_h); cudaGetSymbolAddress((void**)&ysl, g_ys_l);
    cudaGetSymbolAddress((void**)&hbh, g_hb_h); cudaGetSymbolAddress((void**)&hbl, g_hb_l);
    cudaGetSymbolAddress((void**)&ahh, g_ah_h); cudaGetSymbolAddress((void**)&ahl, g_ah_l);
    cudaGetSymbolAddress((void**)&bhh, g_bh_h); cudaGetSymbolAddress((void**)&bhl, g_bh_l);
    cudaGetSymbolAddress((void**)&w1h, g_w1_h); cudaGetSymbolAddress((void**)&w1l, g_w1_l);
    cudaGetSymbolAddress((void**)&w2h, g_w2_h); cudaGetSymbolAddress((void**)&w2l, g_w2_l);

    const int ATTN_SMEM = (2 * KTILE_W + 2 * 768 + 64 + 64) * (int)sizeof(float); // ~107 KB
    cudaFuncSetAttribute(attn_kernel, cudaFuncAttributeMaxDynamicSharedMemorySize, ATTN_SMEM);
    cudaFuncSetAttribute(mma_gemm_bf, cudaFuncAttributeMaxDynamicSharedMemorySize, 4 * STG);

    // 1. weight transposes
    prep_transpose<<<dim3(12, 6, 6), dim3(32, 8)>>>(w_q, w_k, w_v, Tq, Tk, Tv);

    const float invs = (float)(1.0 / sqrt((double)DK_));

    // 2. Ahat + Bhat GEMM tiles + elementwise converts
    precompute_kernel<<<296, 256>>>(Tk, Tq, Tv, fc_w, ahh, ahl, bhh, bhl, invs,
                                    src, src_t, mg_w1, mg_w2,
                                    qth, qtl, ysh, ysl, w1h, w1l, w2h, w2l);

    // 3. Qt = [src|src_t] @ Ahat^T  (768 tiles, K=256)
    mma_gemm_bf<<<296, 256, 4 * STG>>>(
        qth, qtl, 256, ahh, ahl, 256, nullptr,
        Qt, nullptr, nullptr, 768, 256, 1.f, 0, 768, 12,
        768, 0, 0, 0);

    // 4. persistent attention -> Cb hi/lo, attn_w
    attn_kernel<<<296, 256, ATTN_SMEM>>>(Qt, seq, seq_e, seq_t, mask, cbh, cbl, attn_out);

    // 5. Y partials: split-K=2 over heads (768 tiles of K=384)
    mma_gemm_bf<<<296, 256, 4 * STG>>>(
        cbh, cbl, 768, bhh, bhl, 768, nullptr,
        Y, nullptr, nullptr, 384, 384, 1.f, 0, 768, 6,
        384, 384, 384, (size_t)B_ * 384);

    // 6. LayerNorm (sums partials + fc_b) -> YS hi/lo
    ln_kernel<<<B_ / 8, 256>>>(Y, fc_b, ln_g, ln_b, ysh, ysl);

    // 7. Hb = relu(YS @ w1^T + b1)  (128 tiles, K=512) -> hi/lo
    mma_gemm_bf<<<128, 256, 4 * STG>>>(
        ysh, ysl, 512, w1h, w1l, 512, mg_b1,
        nullptr, hbh, hbl, 128, 512, 1.f, 1, 128, 2,
        128, 0, 0, 0);

    // 8. merged = Hb @ w2^T + b2  (128 tiles, K=128)
    mma_gemm_bf<<<128, 256, 4 * STG>>>(
        hbh, hbl, 128, w2h, w2l, 128, mg_b2,
        merged_out, nullptr, nullptr, 128, 128, 1.f, 0, 128, 2,
        128, 0, 0, 0);

    (void)in_sizes; (void)n_in; (void)out_size; (void)seq_t;
}

// round 17
// speedup vs baseline: 1.0872x; 1.0092x over previous
#include <cuda_runtime.h>
#include <cuda_bf16.h>
#include <math.h>
#include <stdint.h>

// Problem constants
#define B_  8192
#define N_  32
#define D_  128
#define M_  384
#define H_  2
#define DK_ 192

typedef __nv_bfloat16 bf16;

// ---------------------------------------------------------------------------
// Static device scratch
// ---------------------------------------------------------------------------
__device__ __align__(16) float g_Tq[2 * 256 * 192];
__device__ __align__(16) float g_Tk[2 * 384 * 192];
__device__ __align__(16) float g_Tv[2 * 384 * 192];
__device__ __align__(16) float g_Qt[(size_t)B_ * 768];        // fp32 (attn input)
__device__ __align__(16) float g_Y[2 * (size_t)B_ * 384];     // fp32 split-K partials

// bf16 hi/lo operand buffers
__device__ __align__(16) bf16 g_qt_h[(size_t)B_ * 256], g_qt_l[(size_t)B_ * 256];   // [src|src_t]
__device__ __align__(16) bf16 g_cb_h[(size_t)B_ * 768], g_cb_l[(size_t)B_ * 768];
__device__ __align__(16) bf16 g_ys_h[(size_t)B_ * 512], g_ys_l[(size_t)B_ * 512];   // [LN(Y)|src]
__device__ __align__(16) bf16 g_hb_h[(size_t)B_ * 128], g_hb_l[(size_t)B_ * 128];
__device__ __align__(16) bf16 g_ah_h[768 * 256], g_ah_l[768 * 256];
__device__ __align__(16) bf16 g_bh_h[384 * 768], g_bh_l[384 * 768];
__device__ __align__(16) bf16 g_w1_h[128 * 512], g_w1_l[128 * 512];
__device__ __align__(16) bf16 g_w2_h[128 * 128], g_w2_l[128 * 128];

// ---------------------------------------------------------------------------
// PTX helpers (baseline PTX: valid at compute_103)
// ---------------------------------------------------------------------------
__device__ __forceinline__ uint32_t smem_u32(const void* p) {
    uint32_t a;
    asm("{ .reg .u64 t; cvta.to.shared.u64 t, %1; cvt.u32.u64 %0, t; }"
        : "=r"(a) : "l"(p));
    return a;
}

__device__ __forceinline__ void mma_bf16(float* d, const uint32_t* a, const uint32_t* b) {
    asm volatile(
        "mma.sync.aligned.m16n8k16.row.col.f32.bf16.bf16.f32 "
        "{%0,%1,%2,%3}, {%4,%5,%6,%7}, {%8,%9}, {%0,%1,%2,%3};"
        : "+f"(d[0]), "+f"(d[1]), "+f"(d[2]), "+f"(d[3])
        : "r"(a[0]), "r"(a[1]), "r"(a[2]), "r"(a[3]), "r"(b[0]), "r"(b[1]));
}

__device__ __forceinline__ void ldmx4(uint32_t* r, uint32_t addr) {
    asm volatile("ldmatrix.sync.aligned.m8n8.x4.shared.b16 {%0,%1,%2,%3}, [%4];"
        : "=r"(r[0]), "=r"(r[1]), "=r"(r[2]), "=r"(r[3]) : "r"(addr));
}

__device__ __forceinline__ void cpa16(uint32_t s, const void* g) {
    asm volatile("cp.async.cg.shared.global [%0], [%1], 16;" :: "r"(s), "l"(g));
}
#define CPA_COMMIT() asm volatile("cp.async.commit_group;")
#define CPA_WAIT2()  asm volatile("cp.async.wait_group 2;")
#define CPA_WAIT1()  asm volatile("cp.async.wait_group 1;")
#define CPA_WAIT0()  asm volatile("cp.async.wait_group 0;")

// fp32 -> bf16 hi/lo split, two elements packed per word
__device__ __forceinline__ void bsplit(float a, float b, uint32_t& hi, uint32_t& lo) {
    bf16 ha = __float2bfloat16_rn(a), hb = __float2bfloat16_rn(b);
    bf16 la = __float2bfloat16_rn(a - __bfloat162float(ha));
    bf16 lb = __float2bfloat16_rn(b - __bfloat162float(hb));
    hi = ((uint32_t)__bfloat16_as_ushort(hb) << 16) | (uint32_t)__bfloat16_as_ushort(ha);
    lo = ((uint32_t)__bfloat16_as_ushort(lb) << 16) | (uint32_t)__bfloat16_as_ushort(la);
}

// ---------------------------------------------------------------------------
// COMPUTE core (warp tile 32x32, BK=32, bf16x3)
// ---------------------------------------------------------------------------
#define STG 24576

__device__ __forceinline__ void compute_ks(
    uint32_t base, int ks, int mw, int nw, int lt, int lr, float acc[2][4][4])
{
    uint32_t Ah[2][4], Al[2][4], Bh[4][2], Bl[4][2];
#pragma unroll
    for (int mt = 0; mt < 2; mt++) {
        int m  = mw + mt * 16 + ((lt & 1) << 3) + lr;
        int cc = ks * 2 + (lt >> 1);
        uint32_t off = (uint32_t)(m * 64 + ((cc ^ ((m >> 1) & 3)) << 4));
        ldmx4(Ah[mt], base + off);
        ldmx4(Al[mt], base + 8192u + off);
    }
#pragma unroll
    for (int p = 0; p < 2; p++) {
        int n  = nw + ((2 * p + (lt >> 1)) << 3) + lr;
        int cc = ks * 2 + (lt & 1);
        uint32_t off = (uint32_t)(n * 64 + ((cc ^ ((n >> 1) & 3)) << 4));
        uint32_t t[4];
        ldmx4(t, base + 16384u + off);
        Bh[2 * p][0] = t[0]; Bh[2 * p][1] = t[1];
        Bh[2 * p + 1][0] = t[2]; Bh[2 * p + 1][1] = t[3];
        ldmx4(t, base + 20480u + off);
        Bl[2 * p][0] = t[0]; Bl[2 * p][1] = t[1];
        Bl[2 * p + 1][0] = t[2]; Bl[2 * p + 1][1] = t[3];
    }
#pragma unroll
    for (int mt = 0; mt < 2; mt++)
#pragma unroll
        for (int nt = 0; nt < 4; nt++) {
            mma_bf16(acc[mt][nt], Ah[mt], Bh[nt]);
            mma_bf16(acc[mt][nt], Ah[mt], Bl[nt]);
            mma_bf16(acc[mt][nt], Al[mt], Bh[nt]);
        }
}

// Epilogue fragment writer (fp32 OR bf16 hi/lo)
__device__ __forceinline__ void epilogue(
    int bm, int bn, int mw, int nw, int lane, float acc[2][4][4],
    const float* bias, float scale, int do_relu,
    float* outf, bf16* ohi, bf16* olo, int ldc)
{
    const int er = lane >> 2, ec = (lane & 3) << 1;
#pragma unroll
    for (int mt = 0; mt < 2; mt++)
#pragma unroll
        for (int nt = 0; nt < 4; nt++) {
            int row = bm + mw + mt * 16 + er;
            int col = bn + nw + nt * 8 + ec;
            float b0 = bias ? bias[col] : 0.f;
            float b1 = bias ? bias[col + 1] : 0.f;
            float v0 = acc[mt][nt][0] * scale + b0;
            float v1 = acc[mt][nt][1] * scale + b1;
            float v2 = acc[mt][nt][2] * scale + b0;
            float v3 = acc[mt][nt][3] * scale + b1;
            if (do_relu) {
                v0 = fmaxf(v0, 0.f); v1 = fmaxf(v1, 0.f);
                v2 = fmaxf(v2, 0.f); v3 = fmaxf(v3, 0.f);
            }
            if (outf) {
                *(float2*)(outf + (size_t)row * ldc + col)       = make_float2(v0, v1);
                *(float2*)(outf + (size_t)(row + 8) * ldc + col) = make_float2(v2, v3);
            } else {
                uint32_t h, l;
                bsplit(v0, v1, h, l);
                *(uint32_t*)(ohi + (size_t)row * ldc + col) = h;
                *(uint32_t*)(olo + (size_t)row * ldc + col) = l;
                bsplit(v2, v3, h, l);
                *(uint32_t*)(ohi + (size_t)(row + 8) * ldc + col) = h;
                *(uint32_t*)(olo + (size_t)(row + 8) * ldc + col) = l;
            }
        }
}

// ---------------------------------------------------------------------------
// GEMM: 4-stage cp.async, tile-stride loop, split-K slices.
// ---------------------------------------------------------------------------
__global__ __launch_bounds__(256, 2) void mma_gemm_bf(
    const bf16* __restrict__ Ahi, const bf16* __restrict__ Alo, int lda,
    const bf16* __restrict__ Whi, const bf16* __restrict__ Wlo, int ldw,
    const float* __restrict__ bias,
    float* __restrict__ outf, bf16* __restrict__ ohi, bf16* __restrict__ olo,
    int ldc, int K, float scale, int do_relu, int nTiles, int gx,
    int perSlice, int aOfs, int wOfs, size_t oOfs)
{
    extern __shared__ __align__(1024) char smbuf[];
    const uint32_t smA = smem_u32(smbuf);

    const int tid  = threadIdx.x;
    const int lane = tid & 31, wid = tid >> 5;
    const int mw = (wid >> 1) * 32;
    const int nw = (wid & 1) * 32;
    const int lt = lane >> 3, lr = lane & 7;
    const int nch = K >> 5;

    const int ar0 = tid >> 2, aq = tid & 3;
    const int ar1 = ar0 + 64;
    const uint32_t aoff0 = (uint32_t)(ar0 * 64 + ((aq ^ ((ar0 >> 1) & 3)) << 4));
    const uint32_t aoff1 = (uint32_t)(ar1 * 64 + ((aq ^ ((ar1 >> 1) & 3)) << 4));
    const uint32_t boff  = aoff0;

    for (int t = blockIdx.x; t < nTiles; t += gridDim.x) {
        const int ksl = t / perSlice;
        const int tt  = t - ksl * perSlice;
        const int bm = (tt / gx) * 128, bn = (tt % gx) * 64;

        const bf16* pAh = Ahi + (size_t)ksl * aOfs;
        const bf16* pAl = Alo + (size_t)ksl * aOfs;
        const bf16* pWh = Whi + (size_t)ksl * wOfs;
        const bf16* pWl = Wlo + (size_t)ksl * wOfs;
        float* pOf = outf ? (outf + (size_t)ksl * oOfs) : (float*)0;

        float acc[2][4][4];
#pragma unroll
        for (int i = 0; i < 2; i++)
#pragma unroll
            for (int j = 0; j < 4; j++)
#pragma unroll
                for (int q = 0; q < 4; q++) acc[i][j][q] = 0.f;

        auto COPY = [&](int c) {
            const uint32_t st = smA + (uint32_t)(c & 3) * STG;
            const int k0 = c << 5;
            cpa16(st + aoff0,         pAh + (size_t)(bm + ar0) * lda + k0 + aq * 8);
            cpa16(st + 8192u + aoff0, pAl + (size_t)(bm + ar0) * lda + k0 + aq * 8);
            cpa16(st + aoff1,         pAh + (size_t)(bm + ar1) * lda + k0 + aq * 8);
            cpa16(st + 8192u + aoff1, pAl + (size_t)(bm + ar1) * lda + k0 + aq * 8);
            cpa16(st + 16384u + boff, pWh + (size_t)(bn + ar0) * ldw + k0 + aq * 8);
            cpa16(st + 20480u + boff, pWl + (size_t)(bn + ar0) * ldw + k0 + aq * 8);
        };

        COPY(0); CPA_COMMIT();
        COPY(1); CPA_COMMIT();
        COPY(2); CPA_COMMIT();

        for (int c = 0; c < nch; c++) {
            CPA_WAIT2();
            __syncthreads();
            const uint32_t base = smA + (uint32_t)(c & 3) * STG;
            compute_ks(base, 0, mw, nw, lt, lr, acc);
            compute_ks(base, 1, mw, nw, lt, lr, acc);
            if (c + 3 < nch) COPY(c + 3);
            CPA_COMMIT();
        }
        CPA_WAIT0();

        epilogue(bm, bn, mw, nw, lane, acc, bias, scale, do_relu, pOf, ohi, olo, ldc);
        __syncthreads();
    }
}

// ---------------------------------------------------------------------------
// fp32-input GEMM body (2-stage, in-loop conversion) for the precompute GEMMs.
// ---------------------------------------------------------------------------
__device__ __forceinline__ void gemm_f32_body(
    const float* __restrict__ A0, int lda,
    const float* __restrict__ W, int ldw,
    bf16* __restrict__ ohi, bf16* __restrict__ olo,
    int ldc, int K, float scale, int bm, int bn, char* smraw)
{
    const int tid  = threadIdx.x;
    const int lane = tid & 31, wid = tid >> 5;
    const int mw = (wid >> 1) * 32;
    const int nw = (wid & 1) * 32;
    const int lt = lane >> 3, lr = lane & 7;

    float acc[2][4][4];
#pragma unroll
    for (int i = 0; i < 2; i++)
#pragma unroll
        for (int j = 0; j < 4; j++)
#pragma unroll
            for (int q = 0; q < 4; q++) acc[i][j][q] = 0.f;

    const uint32_t smA = smem_u32(smraw);
    const int nch = K >> 5;

    float4 ra[4], rb[2];

    auto LOAD = [&](int c) {
        const int k0 = c << 5;
#pragma unroll
        for (int i = 0; i < 4; i++) {
            int lin = tid + (i << 8);
            int r = lin >> 3, q = lin & 7;
            ra[i] = *(const float4*)(A0 + (size_t)(bm + r) * lda + k0 + (q << 2));
        }
#pragma unroll
        for (int i = 0; i < 2; i++) {
            int lin = tid + (i << 8);
            int r = lin >> 3, q = lin & 7;
            rb[i] = *(const float4*)(W + (size_t)(bn + r) * ldw + k0 + (q << 2));
        }
    };

    auto STORE = [&](int s) {
        char* st = smraw + s * STG;
#pragma unroll
        for (int i = 0; i < 4; i++) {
            int lin = tid + (i << 8);
            int r = lin >> 3, q = lin & 7;
            uint32_t h0, l0, h1, l1;
            bsplit(ra[i].x, ra[i].y, h0, l0);
            bsplit(ra[i].z, ra[i].w, h1, l1);
            uint32_t off = (uint32_t)(r * 64 + (((q >> 1) ^ ((r >> 1) & 3)) << 4) + ((q & 1) << 3));
            *(uint2*)(st + off)        = make_uint2(h0, h1);
            *(uint2*)(st + 8192 + off) = make_uint2(l0, l1);
        }
#pragma unroll
        for (int i = 0; i < 2; i++) {
            int lin = tid + (i << 8);
            int r = lin >> 3, q = lin & 7;
            uint32_t h0, l0, h1, l1;
            bsplit(rb[i].x, rb[i].y, h0, l0);
            bsplit(rb[i].z, rb[i].w, h1, l1);
            uint32_t off = (uint32_t)(r * 64 + (((q >> 1) ^ ((r >> 1) & 3)) << 4) + ((q & 1) << 3));
            *(uint2*)(st + 16384 + off) = make_uint2(h0, h1);
            *(uint2*)(st + 20480 + off) = make_uint2(l0, l1);
        }
    };

    LOAD(0); STORE(0); __syncthreads();
    for (int c = 0; c < nch; c++) {
        const int more = (c + 1 < nch);
        if (more) LOAD(c + 1);
        const uint32_t base = smA + (uint32_t)(c & 1) * STG;
        compute_ks(base, 0, mw, nw, lt, lr, acc);
        if (more) STORE((c + 1) & 1);
        compute_ks(base, 1, mw, nw, lt, lr, acc);
        __syncthreads();
    }

    epilogue(bm, bn, mw, nw, lane, acc, nullptr, scale, 0, nullptr, ohi, olo, ldc);
}

// ---------------------------------------------------------------------------
// One launch: CTAs 0..59 compute Ahat + Bhat; CTAs 60.. do elementwise converts.
// ---------------------------------------------------------------------------
__global__ __launch_bounds__(256, 2) void precompute_kernel(
    const float* __restrict__ Tk, const float* __restrict__ Tq,
    const float* __restrict__ Tv, const float* __restrict__ fc_w,
    bf16* __restrict__ ahh, bf16* __restrict__ ahl,
    bf16* __restrict__ bhh, bf16* __restrict__ bhl, float invs,
    const float* __restrict__ src, const float* __restrict__ srct,
    const float* __restrict__ w1, const float* __restrict__ w2,
    bf16* __restrict__ qh, bf16* __restrict__ ql,
    bf16* __restrict__ ysh, bf16* __restrict__ ysl,
    bf16* __restrict__ w1h, bf16* __restrict__ w1l,
    bf16* __restrict__ w2h, bf16* __restrict__ w2l)
{
    __shared__ __align__(1024) char smbuf[2 * STG];
    int id = blockIdx.x;
    if (id < 24) {
        int head = id / 12, t = id % 12;
        gemm_f32_body(Tk + (size_t)head * 384 * 192, 192,
                      Tq + (size_t)head * 256 * 192, 192,
                      ahh + (size_t)head * 384 * 256, ahl + (size_t)head * 384 * 256,
                      256, 192, invs, (t / 4) * 128, (t % 4) * 64, smbuf);
    } else if (id < 60) {
        id -= 24;
        int head = id / 18, t = id % 18;
        gemm_f32_body(fc_w + head * 192, 384,
                      Tv + (size_t)head * 384 * 192, 192,
                      bhh + head * 384, bhl + head * 384,
                      768, 192, 1.f, (t / 6) * 128, (t % 6) * 64, smbuf);
    } else {
        const int nconv = gridDim.x - 60;
        const int stride = nconv * 256;
        for (int idx = (blockIdx.x - 60) * 256 + threadIdx.x;
             idx < B_ * 64; idx += stride) {
            int b = idx >> 6, d2 = idx & 63;
            float2 s  = ((const float2*)src)[(size_t)b * 64 + d2];
            float2 st = ((const float2*)srct)[(size_t)b * 64 + d2];
            uint32_t h, l;
            bsplit(s.x, s.y, h, l);
            ((uint32_t*)qh)[(size_t)b * 128 + d2] = h;
            ((uint32_t*)ql)[(size_t)b * 128 + d2] = l;
            ((uint32_t*)ysh)[(size_t)b * 256 + 192 + d2] = h;
            ((uint32_t*)ysl)[(size_t)b * 256 + 192 + d2] = l;
            bsplit(st.x, st.y, h, l);
            ((uint32_t*)qh)[(size_t)b * 128 + 64 + d2] = h;
            ((uint32_t*)ql)[(size_t)b * 128 + 64 + d2] = l;
            if (idx < 128 * 512 / 2) {
                float2 v = ((const float2*)w1)[idx];
                uint32_t hh, ll;
                bsplit(v.x, v.y, hh, ll);
                ((uint32_t*)w1h)[idx] = hh;
                ((uint32_t*)w1l)[idx] = ll;
            }
            if (idx < 128 * 128 / 2) {
                float2 v = ((const float2*)w2)[idx];
                uint32_t hh, ll;
                bsplit(v.x, v.y, hh, ll);
                ((uint32_t*)w2h)[idx] = hh;
                ((uint32_t*)w2l)[idx] = ll;
            }
        }
    }
}

// ---------------------------------------------------------------------------
// Merged weight transposes
// ---------------------------------------------------------------------------
__global__ void prep_transpose(const float* __restrict__ w_q,
                               const float* __restrict__ w_k,
                               const float* __restrict__ w_v,
                               float* __restrict__ Tq, float* __restrict__ Tk,
                               float* __restrict__ Tv)
{
    __shared__ float tile[32][33];
    const int z = blockIdx.z;
    const int h = z & 1;
    const float* src; float* dst; int cols, split, shift;
    if (z < 2)      { src = w_q; dst = Tq; cols = 256; split = 128; shift = 128; }
    else if (z < 4) { src = w_k; dst = Tk; cols = 384; split = 384; shift = 0; }
    else            { src = w_v; dst = Tv; cols = 384; split = 384; shift = 0; }

    const int c0 = blockIdx.x * 32;
    if (c0 >= cols) return;
    const int d0 = blockIdx.y * 32;
    const int tx = threadIdx.x, ty = threadIdx.y;

#pragma unroll
    for (int r = 0; r < 4; r++) {
        int d = d0 + ty + r * 8;
        int c = c0 + tx;
        int cm = (c < split) ? c : c + shift;
        tile[ty + r * 8][tx] = src[(size_t)(h * 192 + d) * 384 + cm];
    }
    __syncthreads();
#pragma unroll
    for (int r = 0; r < 4; r++) {
        int c = c0 + ty + r * 8;
        int d = d0 + tx;
        dst[(size_t)(h * cols + c) * 192 + d] = tile[tx][ty + r * 8];
    }
}

// ---------------------------------------------------------------------------
// Persistent double-buffered attention (R16 + division-free ISSUE +
// 192-thread float2 C phase with smem-broadcast weights).
// KSTRIDE=392 (≡ 8 mod 32).
// ---------------------------------------------------------------------------
#define KSTRIDE 392
#define KTILE_W (32 * KSTRIDE)

__global__ __launch_bounds__(256, 2) void attn_kernel(
    const float* __restrict__ Qt,
    const float* __restrict__ seq,
    const float* __restrict__ seq_e,
    const float* __restrict__ seq_t,
    const int*   __restrict__ mask,
    bf16* __restrict__ Cbh, bf16* __restrict__ Cbl,
    float* __restrict__ attn_out)
{
    extern __shared__ __align__(1024) char dynsm[];
    float* kb0 = (float*)dynsm;                 // 2 x KTILE_W
    float* qs0 = kb0 + 2 * KTILE_W;             // 2 x 768
    float* sc  = qs0 + 2 * 768;                 // 64
    float* at  = sc + 64;                       // 64

    const int tid = threadIdx.x;
    const int lane = tid & 31, wid = tid >> 5;
    const uint32_t kbb = smem_u32(kb0);
    const uint32_t qsb = smem_u32(qs0);

    const int nb = (B_ - blockIdx.x + gridDim.x - 1) / gridDim.x;

    // Division-free copy mapping: row = tid>>3, quads (tid&7)+8*it.
    const int cr = tid >> 3;      // k row 0..31
    const int cq = tid & 7;       // quad seed 0..7

    auto ISSUE = [&](int b, int s) {
        const uint32_t kd = kbb + (uint32_t)s * (KTILE_W * 4);
        const size_t grow = ((size_t)(b * 32 + cr)) * 128;
#pragma unroll
        for (int it = 0; it < 12; it++) {
            int quad = cq + (it << 3);          // 0..95
            int seg  = quad >> 5;
            int dq   = quad & 31;
            const float* p = (seg == 0) ? seq : ((seg == 1) ? seq_e : seq_t);
            cpa16(kd + (uint32_t)(cr * KSTRIDE + quad * 4) * 4u,
                  p + grow + dq * 4);
        }
        if (tid < 192)
            cpa16(qsb + (uint32_t)s * 3072u + (uint32_t)tid * 16u,
                  Qt + (size_t)b * 768 + tid * 4);
    };

    ISSUE(blockIdx.x, 0); CPA_COMMIT();

    for (int i = 0; i < nb; i++) {
        const int b = blockIdx.x + i * gridDim.x;
        const int more = (i + 1 < nb);
        if (more) { ISSUE(b + gridDim.x, (i + 1) & 1); CPA_COMMIT(); }
        if (more) { CPA_WAIT1(); } else { CPA_WAIT0(); }
        __syncthreads();

        const int s = i & 1;
        const float* kbuf = kb0 + s * KTILE_W;
        const float* qs   = qs0 + s * 768;

        // Scores: warp w owns n = 4w..4w+3; q loaded once per warp per strip.
        {
            const int n0 = wid * 4;
            float a00 = 0.f, a01 = 0.f, a10 = 0.f, a11 = 0.f,
                  a20 = 0.f, a21 = 0.f, a30 = 0.f, a31 = 0.f;
            const float* k0r = kbuf + (n0 + 0) * KSTRIDE;
            const float* k1r = kbuf + (n0 + 1) * KSTRIDE;
            const float* k2r = kbuf + (n0 + 2) * KSTRIDE;
            const float* k3r = kbuf + (n0 + 3) * KSTRIDE;
#pragma unroll
            for (int j0 = 0; j0 < 384; j0 += 32) {
                int j = j0 + lane;
                float q0 = qs[j];
                float q1 = qs[384 + j];
                float k0v = k0r[j], k1v = k1r[j], k2v = k2r[j], k3v = k3r[j];
                a00 += k0v * q0; a01 += k0v * q1;
                a10 += k1v * q0; a11 += k1v * q1;
                a20 += k2v * q0; a21 += k2v * q1;
                a30 += k3v * q0; a31 += k3v * q1;
            }
#pragma unroll
            for (int o = 16; o > 0; o >>= 1) {
                a00 += __shfl_xor_sync(0xffffffffu, a00, o);
                a01 += __shfl_xor_sync(0xffffffffu, a01, o);
                a10 += __shfl_xor_sync(0xffffffffu, a10, o);
                a11 += __shfl_xor_sync(0xffffffffu, a11, o);
                a20 += __shfl_xor_sync(0xffffffffu, a20, o);
                a21 += __shfl_xor_sync(0xffffffffu, a21, o);
                a30 += __shfl_xor_sync(0xffffffffu, a30, o);
                a31 += __shfl_xor_sync(0xffffffffu, a31, o);
            }
            if (lane < 4) {
                int n = n0 + lane;
                bool msk = (mask[b * 32 + n] != 0);
                float s0 = (lane == 0) ? a00 : (lane == 1) ? a10 : (lane == 2) ? a20 : a30;
                float s1 = (lane == 0) ? a01 : (lane == 1) ? a11 : (lane == 2) ? a21 : a31;
                sc[n]      = msk ? -1e10f : s0;
                sc[32 + n] = msk ? -1e10f : s1;
            }
        }
        __syncthreads();

        if (wid < 2) {
            float sv = sc[wid * 32 + lane];
            float m = sv;
#pragma unroll
            for (int o = 16; o > 0; o >>= 1)
                m = fmaxf(m, __shfl_xor_sync(0xffffffffu, m, o));
            float e = expf(sv - m);
            float sum = e;
#pragma unroll
            for (int o = 16; o > 0; o >>= 1)
                sum += __shfl_xor_sync(0xffffffffu, sum, o);
            float p = e / sum;
            at[wid * 32 + lane] = p;
            attn_out[((size_t)wid * B_ + b) * 32 + lane] = p;
        }
        __syncthreads();

        // C phase: 192 threads, 2 cols each (float2); weights via smem broadcast
        if (tid < 192) {
            const int j = tid * 2;
            float c00 = 0.f, c01 = 0.f, c10 = 0.f, c11 = 0.f;
#pragma unroll
            for (int n = 0; n < 32; n++) {
                float2 kv = *(const float2*)(kbuf + n * KSTRIDE + j);
                float w0 = at[n], w1 = at[32 + n];
                c00 += w0 * kv.x; c01 += w0 * kv.y;
                c10 += w1 * kv.x; c11 += w1 * kv.y;
            }
            uint32_t* CH = (uint32_t*)Cbh + (size_t)b * 384;
            uint32_t* CL = (uint32_t*)Cbl + (size_t)b * 384;
            uint32_t h, l;
            bsplit(c00, c01, h, l);
            CH[tid] = h; CL[tid] = l;
            bsplit(c10, c11, h, l);
            CH[192 + tid] = h; CL[192 + tid] = l;
        }
        __syncthreads();   // buffer s fully consumed before iter i+1 overwrites it
    }
}

// ---------------------------------------------------------------------------
// LayerNorm: sums 2 split-K partials + fc_b, writes YS hi/lo
// ---------------------------------------------------------------------------
__global__ __launch_bounds__(256) void ln_kernel(
    const float* __restrict__ Y0,
    const float* __restrict__ fc_b,
    const float* __restrict__ ln_g,
    const float* __restrict__ ln_b,
    bf16* __restrict__ ysh, bf16* __restrict__ ysl)
{
    const int row  = blockIdx.x * 8 + (threadIdx.x >> 5);
    const int lane = threadIdx.x & 31;
    const float* y0 = Y0 + (size_t)row * 384;
    const float* y1 = y0 + (size_t)B_ * 384;

    float2 v[6];
    float s = 0.f;
#pragma unroll
    for (int i = 0; i < 6; i++) {
        int c = 2 * lane + 64 * i;
        float2 a0 = *(const float2*)(y0 + c);
        float2 a1 = *(const float2*)(y1 + c);
        v[i].x = a0.x + a1.x + fc_b[c];
        v[i].y = a0.y + a1.y + fc_b[c + 1];
        s += v[i].x + v[i].y;
    }
#pragma unroll
    for (int o = 16; o > 0; o >>= 1) s += __shfl_xor_sync(0xffffffffu, s, o);
    float mu = s * (1.f / 384.f);

    float q = 0.f;
#pragma unroll
    for (int i = 0; i < 6; i++) {
        float d0 = v[i].x - mu, d1 = v[i].y - mu;
        q += d0 * d0 + d1 * d1;
    }
#pragma unroll
    for (int o = 16; o > 0; o >>= 1) q += __shfl_xor_sync(0xffffffffu, q, o);
    float inv = rsqrtf(q * (1.f / 384.f) + 1e-5f);

#pragma unroll
    for (int i = 0; i < 6; i++) {
        int c = 2 * lane + 64 * i;
        float yy0 = (v[i].x - mu) * inv * ln_g[c] + ln_b[c];
        float yy1 = (v[i].y - mu) * inv * ln_g[c + 1] + ln_b[c + 1];
        uint32_t h, l;
        bsplit(yy0, yy1, h, l);
        ((uint32_t*)ysh)[(size_t)row * 256 + lane + 32 * i] = h;
        ((uint32_t*)ysl)[(size_t)row * 256 + lane + 32 * i] = l;
    }
}

// ---------------------------------------------------------------------------
// Launch
// ---------------------------------------------------------------------------
extern "C" void kernel_launch(void* const* d_in, const int* in_sizes, int n_in,
                              void* d_out, int out_size)
{
    const float* src   = (const float*)d_in[0];
    const float* src_t = (const float*)d_in[1];
    const float* seq   = (const float*)d_in[2];
    const float* seq_t = (const float*)d_in[3];
    const float* seq_e = (const float*)d_in[4];
    const int*   mask  = (const int*)d_in[6];
    const float* w_q   = (const float*)d_in[7];
    const float* w_k   = (const float*)d_in[8];
    const float* w_v   = (const float*)d_in[9];
    const float* fc_w  = (const float*)d_in[10];
    const float* fc_b  = (const float*)d_in[11];
    const float* ln_g  = (const float*)d_in[12];
    const float* ln_b  = (const float*)d_in[13];
    const float* mg_w1 = (const float*)d_in[14];
    const float* mg_b1 = (const float*)d_in[15];
    const float* mg_w2 = (const float*)d_in[16];
    const float* mg_b2 = (const float*)d_in[17];
    float* out = (float*)d_out;
    float* merged_out = out;
    float* attn_out   = out + (size_t)B_ * D_;

    float *Tq, *Tk, *Tv, *Qt, *Y;
    bf16 *qth, *qtl, *cbh, *cbl, *ysh, *ysl, *hbh, *hbl;
    bf16 *ahh, *ahl, *bhh, *bhl, *w1h, *w1l, *w2h, *w2l;
    cudaGetSymbolAddress((void**)&Tq, g_Tq);
    cudaGetSymbolAddress((void**)&Tk, g_Tk);
    cudaGetSymbolAddress((void**)&Tv, g_Tv);
    cudaGetSymbolAddress((void**)&Qt, g_Qt);
    cudaGetSymbolAddress((void**)&Y,  g_Y);
    cudaGetSymbolAddress((void**)&qth, g_qt_h); cudaGetSymbolAddress((void**)&qtl, g_qt_l);
    cudaGetSymbolAddress((void**)&cbh, g_cb_h); cudaGetSymbolAddress((void**)&cbl, g_cb_l);
    cudaGetSymbolAddress((void**)&ysh, g_ys_h); cudaGetSymbolAddress((void**)&ysl, g_ys_l);
    cudaGetSymbolAddress((void**)&hbh, g_hb_h); cudaGetSymbolAddress((void**)&hbl, g_hb_l);
    cudaGetSymbolAddress((void**)&ahh, g_ah_h); cudaGetSymbolAddress((void**)&ahl, g_ah_l);
    cudaGetSymbolAddress((void**)&bhh, g_bh_h); cudaGetSymbolAddress((void**)&bhl, g_bh_l);
    cudaGetSymbolAddress((void**)&w1h, g_w1_h); cudaGetSymbolAddress((void**)&w1l, g_w1_l);
    cudaGetSymbolAddress((void**)&w2h, g_w2_h); cudaGetSymbolAddress((void**)&w2l, g_w2_l);

    const int ATTN_SMEM = (2 * KTILE_W + 2 * 768 + 64 + 64) * (int)sizeof(float); // ~107 KB
    cudaFuncSetAttribute(attn_kernel, cudaFuncAttributeMaxDynamicSharedMemorySize, ATTN_SMEM);
    cudaFuncSetAttribute(mma_gemm_bf, cudaFuncAttributeMaxDynamicSharedMemorySize, 4 * STG);

    // 1. weight transposes
    prep_transpose<<<dim3(12, 6, 6), dim3(32, 8)>>>(w_q, w_k, w_v, Tq, Tk, Tv);

    const float invs = (float)(1.0 / sqrt((double)DK_));

    // 2. Ahat + Bhat GEMM tiles + elementwise converts
    precompute_kernel<<<296, 256>>>(Tk, Tq, Tv, fc_w, ahh, ahl, bhh, bhl, invs,
                                    src, src_t, mg_w1, mg_w2,
                                    qth, qtl, ysh, ysl, w1h, w1l, w2h, w2l);

    // 3. Qt = [src|src_t] @ Ahat^T  (768 tiles, K=256)
    mma_gemm_bf<<<296, 256, 4 * STG>>>(
        qth, qtl, 256, ahh, ahl, 256, nullptr,
        Qt, nullptr, nullptr, 768, 256, 1.f, 0, 768, 12,
        768, 0, 0, 0);

    // 4. persistent attention -> Cb hi/lo, attn_w
    attn_kernel<<<296, 256, ATTN_SMEM>>>(Qt, seq, seq_e, seq_t, mask, cbh, cbl, attn_out);

    // 5. Y partials: split-K=2 over heads (768 tiles of K=384)
    mma_gemm_bf<<<296, 256, 4 * STG>>>(
        cbh, cbl, 768, bhh, bhl, 768, nullptr,
        Y, nullptr, nullptr, 384, 384, 1.f, 0, 768, 6,
        384, 384, 384, (size_t)B_ * 384);

    // 6. LayerNorm (sums partials + fc_b) -> YS hi/lo
    ln_kernel<<<B_ / 8, 256>>>(Y, fc_b, ln_g, ln_b, ysh, ysl);

    // 7. Hb = relu(YS @ w1^T + b1)  (128 tiles, K=512) -> hi/lo
    mma_gemm_bf<<<128, 256, 4 * STG>>>(
        ysh, ysl, 512, w1h, w1l, 512, mg_b1,
        nullptr, hbh, hbl, 128, 512, 1.f, 1, 128, 2,
        128, 0, 0, 0);

    // 8. merged = Hb @ w2^T + b2  (128 tiles, K=128)
    mma_gemm_bf<<<128, 256, 4 * STG>>>(
        hbh, hbl, 128, w2h, w2l, 128, mg_b2,
        merged_out, nullptr, nullptr, 128, 128, 1.f, 0, 128, 2,
        128, 0, 0, 0);

    (void)in_sizes; (void)n_in; (void)out_size; (void)seq_t;
}